// round 2
// baseline (speedup 1.0000x reference)
#include <cuda_runtime.h>
#include <cuda_bf16.h>

// ---------------- problem constants (fixed shapes) ----------------
#define NNODES 50000
#define NEDGES 400000
#define HID    64
#define NREL   230
#define NTS    365
#define NPAIR  (NREL * NTS)      // 83950
#define DIM    128               // 2*HID
#define SLOPE  0.2f

// ---------------- device scratch (static; no runtime alloc) -------
__device__ __align__(16) float d_relpart[NREL * DIM];
__device__ __align__(16) float d_timepart[NTS * DIM];
__device__ __align__(16) float d_V[NPAIR * DIM];          // lrelu(rel_part+time_part+b_rt)
__device__ __align__(16) float d_rtb[NPAIR * DIM];        // V @ W2 + b_fc
__device__ __align__(16) float d_P[NNODES * 2 * DIM];     // [x@W1 | x@W3], row stride 256
__device__ __align__(16) float d_Bcat[DIM * 2 * DIM];     // [W1 | W3], 128 x 256
__device__ int d_counts[NNODES];
__device__ int d_offsets[NNODES + 1];
__device__ int d_cursor[NNODES];
__device__ int d_ssrc[NEDGES];
__device__ int d_spair[NEDGES];

__device__ __forceinline__ float lrelu(float v) {
    return v >= 0.0f ? v : SLOPE * v;
}

// ---------------- tiny projection: rel_part / time_part ----------
__global__ void k_proj(const float* __restrict__ rel_table,
                       const float* __restrict__ time_table,
                       const float* __restrict__ W_rt) {
    int row = blockIdx.x;          // 0..594
    int j = threadIdx.x;           // 0..127
    float acc = 0.0f;
    if (row < NREL) {
        const float* a = rel_table + row * HID;
#pragma unroll
        for (int k = 0; k < HID; k++) acc += a[k] * W_rt[k * DIM + j];
        d_relpart[row * DIM + j] = acc;
    } else {
        int r = row - NREL;
        const float* a = time_table + r * HID;
#pragma unroll
        for (int k = 0; k < HID; k++) acc += a[k] * W_rt[(HID + k) * DIM + j];
        d_timepart[r * DIM + j] = acc;
    }
}

// ---------------- materialize V over all (rel, ts) pairs ----------
__global__ void k_V(const float* __restrict__ b_rt) {
    int idx = blockIdx.x * blockDim.x + threadIdx.x;
    if (idx >= NPAIR * DIM) return;
    int p = idx >> 7;
    int c = idx & 127;
    int r = p / NTS;
    int t = p - r * NTS;
    float v = d_relpart[r * DIM + c] + d_timepart[t * DIM + c] + b_rt[c];
    d_V[idx] = lrelu(v);
}

// ---------------- build Bcat = [W1 | W3] ---------------------------
__global__ void k_bcat(const float* __restrict__ W_fc) {
    int idx = blockIdx.x * blockDim.x + threadIdx.x;
    if (idx >= DIM * 2 * DIM) return;
    int k = idx >> 8;        // 0..127
    int n = idx & 255;       // 0..255
    float v = (n < DIM) ? W_fc[k * DIM + n]
                        : W_fc[(2 * DIM + k) * DIM + (n - DIM)];
    d_Bcat[idx] = v;
}

// ---------------- register-tiled SGEMM: C[M,N] = A[M,K]@B[K,N](+bias)
// BM=128, BN=128, BK=8, 256 threads, 8x8 per thread. N % 128 == 0, K % 8 == 0.
__global__ __launch_bounds__(256) void sgemm128(
    const float* __restrict__ A, const float* __restrict__ B,
    float* __restrict__ C, const float* __restrict__ bias,
    int M, int N, int K)
{
    __shared__ float As[8][128];
    __shared__ float Bs[8][128];

    int bm = blockIdx.y * 128;
    int bn = blockIdx.x * 128;
    int tid = threadIdx.x;
    int tx = tid & 15;          // 0..15 -> col group
    int ty = tid >> 4;          // 0..15 -> row group
    int arow = tid >> 1;        // 0..127
    int acol = (tid & 1) * 4;   // 0 or 4
    int brow = tid >> 5;        // 0..7
    int bcol = (tid & 31) * 4;  // 0..124

    float acc[8][8];
#pragma unroll
    for (int i = 0; i < 8; i++)
#pragma unroll
        for (int j = 0; j < 8; j++) acc[i][j] = 0.0f;

    for (int k0 = 0; k0 < K; k0 += 8) {
        int garow = bm + arow;
        float4 av = make_float4(0.f, 0.f, 0.f, 0.f);
        if (garow < M)
            av = *reinterpret_cast<const float4*>(&A[garow * K + k0 + acol]);
        As[acol + 0][arow] = av.x;
        As[acol + 1][arow] = av.y;
        As[acol + 2][arow] = av.z;
        As[acol + 3][arow] = av.w;

        float4 bv = *reinterpret_cast<const float4*>(&B[(k0 + brow) * N + bn + bcol]);
        *reinterpret_cast<float4*>(&Bs[brow][bcol]) = bv;
        __syncthreads();

#pragma unroll
        for (int kk = 0; kk < 8; kk++) {
            float a[8], b[8];
            *reinterpret_cast<float4*>(&a[0]) = *reinterpret_cast<const float4*>(&As[kk][ty * 8]);
            *reinterpret_cast<float4*>(&a[4]) = *reinterpret_cast<const float4*>(&As[kk][ty * 8 + 4]);
            *reinterpret_cast<float4*>(&b[0]) = *reinterpret_cast<const float4*>(&Bs[kk][tx * 8]);
            *reinterpret_cast<float4*>(&b[4]) = *reinterpret_cast<const float4*>(&Bs[kk][tx * 8 + 4]);
#pragma unroll
            for (int i = 0; i < 8; i++)
#pragma unroll
                for (int j = 0; j < 8; j++)
                    acc[i][j] += a[i] * b[j];
        }
        __syncthreads();
    }

#pragma unroll
    for (int i = 0; i < 8; i++) {
        int grow = bm + ty * 8 + i;
        if (grow >= M) continue;
#pragma unroll
        for (int j4 = 0; j4 < 8; j4 += 4) {
            int gcol = bn + tx * 8 + j4;
            float4 v;
            v.x = acc[i][j4 + 0];
            v.y = acc[i][j4 + 1];
            v.z = acc[i][j4 + 2];
            v.w = acc[i][j4 + 3];
            if (bias) {
                v.x += bias[gcol + 0];
                v.y += bias[gcol + 1];
                v.z += bias[gcol + 2];
                v.w += bias[gcol + 3];
            }
            *reinterpret_cast<float4*>(&C[grow * N + gcol]) = v;
        }
    }
}

// ---------------- counting sort by dst -----------------------------
__global__ void k_zero_counts() {
    int i = blockIdx.x * blockDim.x + threadIdx.x;
    if (i < NNODES) d_counts[i] = 0;
}

__global__ void k_count(const int* __restrict__ edges) {
    int e = blockIdx.x * blockDim.x + threadIdx.x;
    if (e >= NEDGES) return;
    atomicAdd(&d_counts[edges[e * 4 + 1]], 1);
}

__global__ __launch_bounds__(1024) void k_scan() {
    __shared__ int sdata[1024];
    __shared__ int carryS;
    int t = threadIdx.x;
    if (t == 0) carryS = 0;
    __syncthreads();

    for (int base = 0; base < NNODES; base += 1024) {
        int v = (base + t < NNODES) ? d_counts[base + t] : 0;
        sdata[t] = v;
        __syncthreads();
#pragma unroll
        for (int off = 1; off < 1024; off <<= 1) {
            int x2 = (t >= off) ? sdata[t - off] : 0;
            __syncthreads();
            sdata[t] += x2;
            __syncthreads();
        }
        int incl = sdata[t];
        int bc = carryS;
        if (base + t < NNODES) {
            int excl = bc + incl - v;
            d_offsets[base + t] = excl;
            d_cursor[base + t] = excl;
        }
        int tot = sdata[1023];
        __syncthreads();
        if (t == 0) carryS = bc + tot;
        __syncthreads();
    }
    if (t == 0) d_offsets[NNODES] = carryS;
}

__global__ void k_scatter(const int* __restrict__ edges) {
    int e = blockIdx.x * blockDim.x + threadIdx.x;
    if (e >= NEDGES) return;
    int src = edges[e * 4 + 0];
    int dst = edges[e * 4 + 1];
    int rel = edges[e * 4 + 2];
    int ts  = edges[e * 4 + 3];
    int pos = atomicAdd(&d_cursor[dst], 1);
    d_ssrc[pos] = src;
    d_spair[pos] = rel * NTS + ts;
}

// ---------------- aggregation: warp per node, no atomics -----------
__global__ __launch_bounds__(256) void k_agg(float* __restrict__ out) {
    int warp = (blockIdx.x * blockDim.x + threadIdx.x) >> 5;
    int lane = threadIdx.x & 31;
    if (warp >= NNODES) return;

    int s0 = d_offsets[warp];
    int s1 = d_offsets[warp + 1];

    const float4* P4 = reinterpret_cast<const float4*>(d_P);
    const float4* R4 = reinterpret_cast<const float4*>(d_rtb);

    // P3[dst] term: same for every edge of this node — load once.
    float4 c3 = P4[warp * 64 + 32 + lane];

    float ax = 0.f, ay = 0.f, az = 0.f, aw = 0.f;
    for (int i = s0; i < s1; i++) {
        int s = __ldg(&d_ssrc[i]);
        int pr = __ldg(&d_spair[i]);
        float4 a = __ldg(&P4[s * 64 + lane]);
        float4 b = __ldg(&R4[pr * 32 + lane]);
        float vx = a.x + b.x + c3.x;
        float vy = a.y + b.y + c3.y;
        float vz = a.z + b.z + c3.z;
        float vw = a.w + b.w + c3.w;
        ax += lrelu(vx);
        ay += lrelu(vy);
        az += lrelu(vz);
        aw += lrelu(vw);
    }
    int cnt = s1 - s0;
    float inv = 1.0f / (float)(cnt > 0 ? cnt : 1);
    float4 r;
    r.x = ax * inv; r.y = ay * inv; r.z = az * inv; r.w = aw * inv;
    reinterpret_cast<float4*>(out)[warp * 32 + lane] = r;
}

// ---------------- launcher ----------------------------------------
extern "C" void kernel_launch(void* const* d_in, const int* in_sizes, int n_in,
                              void* d_out, int out_size) {
    const float* x          = (const float*)d_in[0];
    const float* rel_table  = (const float*)d_in[1];
    const float* time_table = (const float*)d_in[2];
    const float* W_rt       = (const float*)d_in[3];
    const float* b_rt       = (const float*)d_in[4];
    const float* W_fc       = (const float*)d_in[5];
    const float* b_fc       = (const float*)d_in[6];
    const int*   edges      = (const int*)d_in[7];
    float* out = (float*)d_out;

    void *pV, *pRtb, *pP, *pBcat;
    cudaGetSymbolAddress(&pV, d_V);
    cudaGetSymbolAddress(&pRtb, d_rtb);
    cudaGetSymbolAddress(&pP, d_P);
    cudaGetSymbolAddress(&pBcat, d_Bcat);

    // small projections + pair table
    k_proj<<<NREL + NTS, DIM>>>(rel_table, time_table, W_rt);
    k_bcat<<<(DIM * 2 * DIM + 255) / 256, 256>>>(W_fc);
    k_V<<<(NPAIR * DIM + 255) / 256, 256>>>(b_rt);

    // P = x @ [W1 | W3]   (50000 x 256, K=128)
    {
        dim3 grid(2, (NNODES + 127) / 128);
        sgemm128<<<grid, 256>>>(x, (const float*)pBcat, (float*)pP, nullptr,
                                NNODES, 2 * DIM, DIM);
    }
    // rtb = V @ W2 + b_fc  (83950 x 128, K=128); W2 = W_fc rows 128..255 (contiguous)
    {
        dim3 grid(1, (NPAIR + 127) / 128);
        sgemm128<<<grid, 256>>>((const float*)pV, W_fc + DIM * DIM, (float*)pRtb,
                                b_fc, NPAIR, DIM, DIM);
    }

    // counting sort of edges by dst
    k_zero_counts<<<(NNODES + 255) / 256, 256>>>();
    k_count<<<(NEDGES + 255) / 256, 256>>>(edges);
    k_scan<<<1, 1024>>>();
    k_scatter<<<(NEDGES + 255) / 256, 256>>>(edges);

    // aggregation (writes every output element; fuses mean)
    k_agg<<<(NNODES * 32 + 255) / 256, 256>>>(out);
}

// round 5
// speedup vs baseline: 1.5235x; 1.5235x over previous
#include <cuda_runtime.h>
#include <cuda_bf16.h>
#include <cstdint>

// ---------------- problem constants (fixed shapes) ----------------
#define NNODES 50000
#define NEDGES 400000
#define HID    64
#define NREL   230
#define NTS    365
#define NPAIR  (NREL * NTS)      // 83950
#define DIM    128               // 2*HID
#define SLOPE  0.2f

// ---------------- device scratch (static; no runtime alloc) -------
__device__ __align__(16) float d_relpart[NREL * DIM];
__device__ __align__(16) float d_timepart[NTS * DIM];
__device__ __align__(16) float d_P[NNODES * 2 * DIM];     // [x@W1 | x@W3], row stride 256
__device__ __align__(16) float d_rtb[NPAIR * DIM];        // V @ W2 (no bias)
__device__ __align__(16) __nv_bfloat16 d_xhi[NNODES * DIM];
__device__ __align__(16) __nv_bfloat16 d_xlo[NNODES * DIM];
__device__ __align__(16) __nv_bfloat16 d_vhi[NPAIR * DIM];
__device__ __align__(16) __nv_bfloat16 d_vlo[NPAIR * DIM];
__device__ __align__(16) __nv_bfloat16 d_bT_hi[2 * DIM * DIM];   // [W1|W3]^T : [256][128]
__device__ __align__(16) __nv_bfloat16 d_bT_lo[2 * DIM * DIM];
__device__ __align__(16) __nv_bfloat16 d_w2T_hi[DIM * DIM];      // W2^T : [128][128]
__device__ __align__(16) __nv_bfloat16 d_w2T_lo[DIM * DIM];
__device__ int d_counts[NNODES];
__device__ int d_offsets[NNODES + 1];
__device__ int d_cursor[NNODES];
__device__ int d_ssrc[NEDGES];
__device__ int d_spair[NEDGES];

__device__ __forceinline__ float lrelu(float v) {
    return v >= 0.0f ? v : SLOPE * v;
}

__device__ __forceinline__ uint32_t smem_u32(const void* p) {
    uint32_t a;
    asm("{ .reg .u64 t; cvta.to.shared.u64 t, %1; cvt.u32.u64 %0, t; }"
        : "=r"(a) : "l"(p));
    return a;
}

__device__ __forceinline__ void ldsm4(uint32_t* r, uint32_t addr) {
    asm volatile("ldmatrix.sync.aligned.m8n8.x4.shared.b16 {%0,%1,%2,%3}, [%4];"
                 : "=r"(r[0]), "=r"(r[1]), "=r"(r[2]), "=r"(r[3]) : "r"(addr));
}

__device__ __forceinline__ void mma_bf16(float* d, const uint32_t* a, const uint32_t* b) {
    asm volatile(
        "mma.sync.aligned.m16n8k16.row.col.f32.bf16.bf16.f32 "
        "{%0,%1,%2,%3}, {%4,%5,%6,%7}, {%8,%9}, {%0,%1,%2,%3};"
        : "+f"(d[0]), "+f"(d[1]), "+f"(d[2]), "+f"(d[3])
        : "r"(a[0]), "r"(a[1]), "r"(a[2]), "r"(a[3]), "r"(b[0]), "r"(b[1]));
}

// ---------------- tiny projection: rel_part / time_part ----------
__global__ void k_proj(const float* __restrict__ rel_table,
                       const float* __restrict__ time_table,
                       const float* __restrict__ W_rt) {
    int row = blockIdx.x;
    int j = threadIdx.x;
    float acc = 0.0f;
    if (row < NREL) {
        const float* a = rel_table + row * HID;
#pragma unroll
        for (int k = 0; k < HID; k++) acc += a[k] * W_rt[k * DIM + j];
        d_relpart[row * DIM + j] = acc;
    } else {
        int r = row - NREL;
        const float* a = time_table + r * HID;
#pragma unroll
        for (int k = 0; k < HID; k++) acc += a[k] * W_rt[(HID + k) * DIM + j];
        d_timepart[r * DIM + j] = acc;
    }
}

// ---------------- split helpers ------------------------------------
__device__ __forceinline__ void bf16_split(float v, __nv_bfloat16& hi, __nv_bfloat16& lo) {
    hi = __float2bfloat16_rn(v);
    lo = __float2bfloat16_rn(v - __bfloat162float(hi));
}

// ---------------- V = lrelu(relpart+timepart+b_rt), split to bf16 --
__global__ void k_V_bf16(const float* __restrict__ b_rt) {
    int idx = blockIdx.x * blockDim.x + threadIdx.x;   // over NPAIR*32 (4 cols each)
    if (idx >= NPAIR * 32) return;
    int p = idx >> 5;
    int c0 = (idx & 31) * 4;
    int r = p / NTS;
    int t = p - r * NTS;
    const float4 rv = *reinterpret_cast<const float4*>(&d_relpart[r * DIM + c0]);
    const float4 tv = *reinterpret_cast<const float4*>(&d_timepart[t * DIM + c0]);
    const float4 bv = *reinterpret_cast<const float4*>(&b_rt[c0]);
    float v[4] = { lrelu(rv.x + tv.x + bv.x), lrelu(rv.y + tv.y + bv.y),
                   lrelu(rv.z + tv.z + bv.z), lrelu(rv.w + tv.w + bv.w) };
    __nv_bfloat16 h[4], l[4];
#pragma unroll
    for (int i = 0; i < 4; i++) bf16_split(v[i], h[i], l[i]);
    *reinterpret_cast<__nv_bfloat162*>(&d_vhi[p * DIM + c0])     = __nv_bfloat162(h[0], h[1]);
    *reinterpret_cast<__nv_bfloat162*>(&d_vhi[p * DIM + c0 + 2]) = __nv_bfloat162(h[2], h[3]);
    *reinterpret_cast<__nv_bfloat162*>(&d_vlo[p * DIM + c0])     = __nv_bfloat162(l[0], l[1]);
    *reinterpret_cast<__nv_bfloat162*>(&d_vlo[p * DIM + c0 + 2]) = __nv_bfloat162(l[2], l[3]);
}

// ---------------- split x to bf16 hi/lo ---------------------------
__global__ void k_split_x(const float* __restrict__ x) {
    int idx = blockIdx.x * blockDim.x + threadIdx.x;   // over NNODES*32 (4 each)
    if (idx >= NNODES * 32) return;
    int e0 = idx * 4;
    float4 v = *reinterpret_cast<const float4*>(&x[e0]);
    __nv_bfloat16 h[4], l[4];
    bf16_split(v.x, h[0], l[0]); bf16_split(v.y, h[1], l[1]);
    bf16_split(v.z, h[2], l[2]); bf16_split(v.w, h[3], l[3]);
    *reinterpret_cast<__nv_bfloat162*>(&d_xhi[e0])     = __nv_bfloat162(h[0], h[1]);
    *reinterpret_cast<__nv_bfloat162*>(&d_xhi[e0 + 2]) = __nv_bfloat162(h[2], h[3]);
    *reinterpret_cast<__nv_bfloat162*>(&d_xlo[e0])     = __nv_bfloat162(l[0], l[1]);
    *reinterpret_cast<__nv_bfloat162*>(&d_xlo[e0 + 2]) = __nv_bfloat162(l[2], l[3]);
}

// ---------------- transpose + split weights -----------------------
__global__ void k_wT(const float* __restrict__ W_fc) {
    int idx = blockIdx.x * blockDim.x + threadIdx.x;
    if (idx < 2 * DIM * DIM) {
        int n = idx >> 7, k = idx & 127;
        float v = (n < DIM) ? W_fc[k * DIM + n]
                            : W_fc[(2 * DIM + k) * DIM + (n - DIM)];
        __nv_bfloat16 h, l; bf16_split(v, h, l);
        d_bT_hi[idx] = h; d_bT_lo[idx] = l;
    } else if (idx < 3 * DIM * DIM) {
        int j = idx - 2 * DIM * DIM;
        int n = j >> 7, k = j & 127;
        float v = W_fc[(DIM + k) * DIM + n];
        __nv_bfloat16 h, l; bf16_split(v, h, l);
        d_w2T_hi[j] = h; d_w2T_lo[j] = l;
    }
}

// ---------------- HMMA bf16x3 GEMM --------------------------------
// C[M, ldc] (cols bn..bn+127) = (Ahi+Alo)[M,128] x (Bhi+Blo [N,128])^T
// 256 threads = 8 warps; warp tile 32x64; BK=32; mma.sync m16n8k16.
#define PITCH 40   // halves per smem row (80B): conflict-free for ldmatrix

__global__ __launch_bounds__(256, 2) void hmma_gemm(
    const __nv_bfloat16* __restrict__ Ahi, const __nv_bfloat16* __restrict__ Alo,
    const __nv_bfloat16* __restrict__ Bhi, const __nv_bfloat16* __restrict__ Blo,
    float* __restrict__ C, int M, int ldc)
{
    __shared__ __align__(16) __nv_bfloat16 sAh[128 * PITCH];
    __shared__ __align__(16) __nv_bfloat16 sAl[128 * PITCH];
    __shared__ __align__(16) __nv_bfloat16 sBh[128 * PITCH];
    __shared__ __align__(16) __nv_bfloat16 sBl[128 * PITCH];

    const int tid = threadIdx.x;
    const int wid = tid >> 5;
    const int lane = tid & 31;
    const int bm = blockIdx.y * 128;
    const int bn = blockIdx.x * 128;
    const int wm = (wid & 3) * 32;        // warp row offset
    const int wn = (wid >> 2) * 64;       // warp col offset

    const uint32_t uAh = smem_u32(sAh);
    const uint32_t uAl = smem_u32(sAl);
    const uint32_t uBh = smem_u32(sBh);
    const uint32_t uBl = smem_u32(sBl);

    float acc[2][8][4];
#pragma unroll
    for (int i = 0; i < 2; i++)
#pragma unroll
        for (int j = 0; j < 8; j++)
#pragma unroll
            for (int k = 0; k < 4; k++) acc[i][j][k] = 0.0f;

    const uint4 zero4 = make_uint4(0, 0, 0, 0);

    for (int k0 = 0; k0 < DIM; k0 += 32) {
        // stage A / B chunk: 128 rows x 32 halves each
#pragma unroll
        for (int i = tid; i < 512; i += 256) {
            int row = i >> 2;
            int c = (i & 3) * 8;
            int grow = bm + row;
            uint4 vh = zero4, vl = zero4;
            if (grow < M) {
                vh = *reinterpret_cast<const uint4*>(Ahi + grow * DIM + k0 + c);
                vl = *reinterpret_cast<const uint4*>(Alo + grow * DIM + k0 + c);
            }
            *reinterpret_cast<uint4*>(&sAh[row * PITCH + c]) = vh;
            *reinterpret_cast<uint4*>(&sAl[row * PITCH + c]) = vl;
            uint4 wh = *reinterpret_cast<const uint4*>(Bhi + (bn + row) * DIM + k0 + c);
            uint4 wl = *reinterpret_cast<const uint4*>(Blo + (bn + row) * DIM + k0 + c);
            *reinterpret_cast<uint4*>(&sBh[row * PITCH + c]) = wh;
            *reinterpret_cast<uint4*>(&sBl[row * PITCH + c]) = wl;
        }
        __syncthreads();

#pragma unroll
        for (int ks = 0; ks < 2; ks++) {
            // A fragments for 2 m-tiles (hi & lo)
            uint32_t ah[2][4], al[2][4];
#pragma unroll
            for (int mt = 0; mt < 2; mt++) {
                int row = wm + mt * 16 + (lane & 15);
                int koff = ks * 16 + ((lane >> 4) << 3);
                uint32_t off = (uint32_t)(row * PITCH + koff) * 2;
                ldsm4(ah[mt], uAh + off);
                ldsm4(al[mt], uAl + off);
            }
            // B fragments: 4 pairs of n-tiles
#pragma unroll
            for (int np = 0; np < 4; np++) {
                int mat = lane >> 3;
                int row = wn + np * 16 + ((mat >> 1) << 3) + (lane & 7);
                int koff = ks * 16 + ((mat & 1) << 3);
                uint32_t off = (uint32_t)(row * PITCH + koff) * 2;
                uint32_t bh[4], bl[4];
                ldsm4(bh, uBh + off);
                ldsm4(bl, uBl + off);
#pragma unroll
                for (int mt = 0; mt < 2; mt++) {
                    mma_bf16(acc[mt][np * 2],     ah[mt], &bh[0]);
                    mma_bf16(acc[mt][np * 2],     ah[mt], &bl[0]);
                    mma_bf16(acc[mt][np * 2],     al[mt], &bh[0]);
                    mma_bf16(acc[mt][np * 2 + 1], ah[mt], &bh[2]);
                    mma_bf16(acc[mt][np * 2 + 1], ah[mt], &bl[2]);
                    mma_bf16(acc[mt][np * 2 + 1], al[mt], &bh[2]);
                }
            }
        }
        __syncthreads();
    }

    // epilogue: direct float2 stores
    const int tr = lane >> 2;
    const int tc = (lane & 3) * 2;
#pragma unroll
    for (int mt = 0; mt < 2; mt++) {
        int grow0 = bm + wm + mt * 16 + tr;
        int grow1 = grow0 + 8;
#pragma unroll
        for (int nt = 0; nt < 8; nt++) {
            int gcol = bn + wn + nt * 8 + tc;
            if (grow0 < M) {
                float2 v0 = make_float2(acc[mt][nt][0], acc[mt][nt][1]);
                *reinterpret_cast<float2*>(&C[grow0 * ldc + gcol]) = v0;
            }
            if (grow1 < M) {
                float2 v1 = make_float2(acc[mt][nt][2], acc[mt][nt][3]);
                *reinterpret_cast<float2*>(&C[grow1 * ldc + gcol]) = v1;
            }
        }
    }
}

// ---------------- counting sort by dst -----------------------------
__global__ void k_zero_counts() {
    int i = blockIdx.x * blockDim.x + threadIdx.x;
    if (i < NNODES) d_counts[i] = 0;
}

__global__ void k_count(const int* __restrict__ edges) {
    int e = blockIdx.x * blockDim.x + threadIdx.x;
    if (e >= NEDGES) return;
    int4 ed = reinterpret_cast<const int4*>(edges)[e];
    atomicAdd(&d_counts[ed.y], 1);
}

__global__ __launch_bounds__(1024) void k_scan() {
    __shared__ int wsum[32];
    const int CH = 49;                      // 1024*49 = 50176 >= 50000
    int t = threadIdx.x;
    int base = t * CH;
    int s = 0;
    for (int i = 0; i < CH; i++) {
        int j = base + i;
        if (j < NNODES) s += d_counts[j];
    }
    int lane = t & 31, w = t >> 5;
    int v = s;
#pragma unroll
    for (int o = 1; o < 32; o <<= 1) {
        int u = __shfl_up_sync(0xFFFFFFFFu, v, o);
        if (lane >= o) v += u;
    }
    if (lane == 31) wsum[w] = v;
    __syncthreads();
    if (w == 0) {
        int x2 = wsum[lane];
#pragma unroll
        for (int o = 1; o < 32; o <<= 1) {
            int u = __shfl_up_sync(0xFFFFFFFFu, x2, o);
            if (lane >= o) x2 += u;
        }
        wsum[lane] = x2;
    }
    __syncthreads();
    int excl = v - s + (w > 0 ? wsum[w - 1] : 0);
    int run = excl;
    for (int i = 0; i < CH; i++) {
        int j = base + i;
        if (j < NNODES) {
            d_offsets[j] = run;
            d_cursor[j] = run;
            run += d_counts[j];
        }
    }
    if (t == 1023) d_offsets[NNODES] = run;
}

__global__ void k_scatter(const int* __restrict__ edges) {
    int e = blockIdx.x * blockDim.x + threadIdx.x;
    if (e >= NEDGES) return;
    int4 ed = reinterpret_cast<const int4*>(edges)[e];
    int pos = atomicAdd(&d_cursor[ed.y], 1);
    d_ssrc[pos] = ed.x;
    d_spair[pos] = ed.z * NTS + ed.w;
}

// ---------------- aggregation: warp per node, no atomics -----------
__global__ __launch_bounds__(256) void k_agg(float* __restrict__ out,
                                             const float* __restrict__ b_fc) {
    int warp = (blockIdx.x * blockDim.x + threadIdx.x) >> 5;
    int lane = threadIdx.x & 31;
    if (warp >= NNODES) return;

    int s0 = d_offsets[warp];
    int s1 = d_offsets[warp + 1];

    const float4* P4 = reinterpret_cast<const float4*>(d_P);
    const float4* R4 = reinterpret_cast<const float4*>(d_rtb);

    float4 bias4 = reinterpret_cast<const float4*>(b_fc)[lane];
    float4 c3 = P4[warp * 64 + 32 + lane];
    c3.x += bias4.x; c3.y += bias4.y; c3.z += bias4.z; c3.w += bias4.w;

    float ax = 0.f, ay = 0.f, az = 0.f, aw = 0.f;
    for (int i = s0; i < s1; i++) {
        int s = __ldg(&d_ssrc[i]);
        int pr = __ldg(&d_spair[i]);
        float4 a = __ldg(&P4[s * 64 + lane]);
        float4 b = __ldg(&R4[pr * 32 + lane]);
        ax += lrelu(a.x + b.x + c3.x);
        ay += lrelu(a.y + b.y + c3.y);
        az += lrelu(a.z + b.z + c3.z);
        aw += lrelu(a.w + b.w + c3.w);
    }
    int cnt = s1 - s0;
    float inv = 1.0f / (float)(cnt > 0 ? cnt : 1);
    float4 r;
    r.x = ax * inv; r.y = ay * inv; r.z = az * inv; r.w = aw * inv;
    reinterpret_cast<float4*>(out)[warp * 32 + lane] = r;
}

// ---------------- launcher ----------------------------------------
extern "C" void kernel_launch(void* const* d_in, const int* in_sizes, int n_in,
                              void* d_out, int out_size) {
    const float* x          = (const float*)d_in[0];
    const float* rel_table  = (const float*)d_in[1];
    const float* time_table = (const float*)d_in[2];
    const float* W_rt       = (const float*)d_in[3];
    const float* b_rt       = (const float*)d_in[4];
    const float* W_fc       = (const float*)d_in[5];
    const float* b_fc       = (const float*)d_in[6];
    const int*   edges      = (const int*)d_in[7];
    float* out = (float*)d_out;

    void *pP, *pRtb, *pXhi, *pXlo, *pVhi, *pVlo, *pBh, *pBl, *pW2h, *pW2l;
    cudaGetSymbolAddress(&pP, d_P);
    cudaGetSymbolAddress(&pRtb, d_rtb);
    cudaGetSymbolAddress(&pXhi, d_xhi);
    cudaGetSymbolAddress(&pXlo, d_xlo);
    cudaGetSymbolAddress(&pVhi, d_vhi);
    cudaGetSymbolAddress(&pVlo, d_vlo);
    cudaGetSymbolAddress(&pBh, d_bT_hi);
    cudaGetSymbolAddress(&pBl, d_bT_lo);
    cudaGetSymbolAddress(&pW2h, d_w2T_hi);
    cudaGetSymbolAddress(&pW2l, d_w2T_lo);

    // prep: projections, V pairs, splits, weight transposes
    k_proj<<<NREL + NTS, DIM>>>(rel_table, time_table, W_rt);
    k_wT<<<(3 * DIM * DIM + 255) / 256, 256>>>(W_fc);
    k_split_x<<<(NNODES * 32 + 255) / 256, 256>>>(x);
    k_V_bf16<<<(NPAIR * 32 + 255) / 256, 256>>>(b_rt);

    // P = x @ [W1 | W3]   (HMMA bf16x3)
    {
        dim3 grid(2, (NNODES + 127) / 128);
        hmma_gemm<<<grid, 256>>>(
            (const __nv_bfloat16*)pXhi, (const __nv_bfloat16*)pXlo,
            (const __nv_bfloat16*)pBh,  (const __nv_bfloat16*)pBl,
            (float*)pP, NNODES, 2 * DIM);
    }
    // rtb = V @ W2 (bias folded into k_agg)
    {
        dim3 grid(1, (NPAIR + 127) / 128);
        hmma_gemm<<<grid, 256>>>(
            (const __nv_bfloat16*)pVhi, (const __nv_bfloat16*)pVlo,
            (const __nv_bfloat16*)pW2h, (const __nv_bfloat16*)pW2l,
            (float*)pRtb, NPAIR, DIM);
    }

    // counting sort of edges by dst
    k_zero_counts<<<(NNODES + 255) / 256, 256>>>();
    k_count<<<(NEDGES + 255) / 256, 256>>>(edges);
    k_scan<<<1, 1024>>>();
    k_scatter<<<(NEDGES + 255) / 256, 256>>>(edges);

    // aggregation (fuses bias + lrelu + mean)
    k_agg<<<(NNODES * 32 + 255) / 256, 256>>>(out, b_fc);
}

// round 7
// speedup vs baseline: 1.6039x; 1.0528x over previous
#include <cuda_runtime.h>
#include <cuda_bf16.h>
#include <cstdint>

// ---------------- problem constants (fixed shapes) ----------------
#define NNODES 50000
#define NEDGES 400000
#define HID    64
#define NREL   230
#define NTS    365
#define NPAIR  (NREL * NTS)      // 83950
#define DIM    128               // 2*HID
#define SLOPE  0.2f

// ---------------- device scratch (static; no runtime alloc) -------
__device__ __align__(16) float d_relpart[NREL * DIM];
__device__ __align__(16) float d_timepart[NTS * DIM];
__device__ __align__(16) float d_P[NNODES * 2 * DIM];     // [x@W1 | x@W3], row stride 256
__device__ __align__(16) float d_rtb[NPAIR * DIM];        // V @ W2 (no bias)
__device__ __align__(16) __nv_bfloat16 d_bT_hi[2 * DIM * DIM];   // [W1|W3]^T : [256][128]
__device__ __align__(16) __nv_bfloat16 d_bT_lo[2 * DIM * DIM];
__device__ __align__(16) __nv_bfloat16 d_w2T_hi[DIM * DIM];      // W2^T : [128][128]
__device__ __align__(16) __nv_bfloat16 d_w2T_lo[DIM * DIM];
__device__ int d_counts[NNODES];
__device__ int d_offsets[NNODES + 1];
__device__ int d_cursor[NNODES];
__device__ int d_ssrc[NEDGES];
__device__ int d_spair[NEDGES];

__device__ __forceinline__ float lrelu(float v) {
    return v >= 0.0f ? v : SLOPE * v;
}

__device__ __forceinline__ uint32_t smem_u32(const void* p) {
    uint32_t a;
    asm("{ .reg .u64 t; cvta.to.shared.u64 t, %1; cvt.u32.u64 %0, t; }"
        : "=r"(a) : "l"(p));
    return a;
}

__device__ __forceinline__ void ldsm4(uint32_t* r, uint32_t addr) {
    asm volatile("ldmatrix.sync.aligned.m8n8.x4.shared.b16 {%0,%1,%2,%3}, [%4];"
                 : "=r"(r[0]), "=r"(r[1]), "=r"(r[2]), "=r"(r[3]) : "r"(addr));
}

__device__ __forceinline__ void mma_bf16(float* d, const uint32_t* a, const uint32_t* b) {
    asm volatile(
        "mma.sync.aligned.m16n8k16.row.col.f32.bf16.bf16.f32 "
        "{%0,%1,%2,%3}, {%4,%5,%6,%7}, {%8,%9}, {%0,%1,%2,%3};"
        : "+f"(d[0]), "+f"(d[1]), "+f"(d[2]), "+f"(d[3])
        : "r"(a[0]), "r"(a[1]), "r"(a[2]), "r"(a[3]), "r"(b[0]), "r"(b[1]));
}

// ---------------- tiny projection: rel_part / time_part ----------
__global__ void k_proj(const float* __restrict__ rel_table,
                       const float* __restrict__ time_table,
                       const float* __restrict__ W_rt) {
    int row = blockIdx.x;
    int j = threadIdx.x;
    float acc = 0.0f;
    if (row < NREL) {
        const float* a = rel_table + row * HID;
#pragma unroll
        for (int k = 0; k < HID; k++) acc += a[k] * W_rt[k * DIM + j];
        d_relpart[row * DIM + j] = acc;
    } else {
        int r = row - NREL;
        const float* a = time_table + r * HID;
#pragma unroll
        for (int k = 0; k < HID; k++) acc += a[k] * W_rt[(HID + k) * DIM + j];
        d_timepart[r * DIM + j] = acc;
    }
}

// ---------------- split helpers ------------------------------------
__device__ __forceinline__ void bf16_split(float v, __nv_bfloat16& hi, __nv_bfloat16& lo) {
    hi = __float2bfloat16_rn(v);
    lo = __float2bfloat16_rn(v - __bfloat162float(hi));
}

// ---------------- transpose + split weights -----------------------
__global__ void k_wT(const float* __restrict__ W_fc) {
    int idx = blockIdx.x * blockDim.x + threadIdx.x;
    if (idx < 2 * DIM * DIM) {
        int n = idx >> 7, k = idx & 127;
        float v = (n < DIM) ? W_fc[k * DIM + n]
                            : W_fc[(2 * DIM + k) * DIM + (n - DIM)];
        __nv_bfloat16 h, l; bf16_split(v, h, l);
        d_bT_hi[idx] = h; d_bT_lo[idx] = l;
    } else if (idx < 3 * DIM * DIM) {
        int j = idx - 2 * DIM * DIM;
        int n = j >> 7, k = j & 127;
        float v = W_fc[(DIM + k) * DIM + n];
        __nv_bfloat16 h, l; bf16_split(v, h, l);
        d_w2T_hi[j] = h; d_w2T_lo[j] = l;
    }
}

// ---------------- HMMA bf16x3 GEMM with fused A construction ------
// MODE 0: A row = x[grow] (fp32, split in staging)
// MODE 1: A row = lrelu(relpart[p/NTS] + timepart[p%NTS] + b_rt)  (pair p = grow)
// C[M, ldc] (cols bn..bn+127) = A x (Bhi+Blo [N,128])^T
// 256 threads = 8 warps; warp tile 32x64; BK=32; mma.sync m16n8k16.
#define PITCH 40   // halves per smem row (80B): conflict-free for ldmatrix

template <int MODE>
__global__ __launch_bounds__(256, 2) void hmma_fused(
    const float* __restrict__ Asrc,                 // MODE0: x
    const __nv_bfloat16* __restrict__ Bhi,
    const __nv_bfloat16* __restrict__ Blo,
    const float* __restrict__ b_rt,                 // MODE1 only
    float* __restrict__ C, int M, int ldc)
{
    __shared__ __align__(16) __nv_bfloat16 sAh[128 * PITCH];
    __shared__ __align__(16) __nv_bfloat16 sAl[128 * PITCH];
    __shared__ __align__(16) __nv_bfloat16 sBh[128 * PITCH];
    __shared__ __align__(16) __nv_bfloat16 sBl[128 * PITCH];

    const int tid = threadIdx.x;
    const int wid = tid >> 5;
    const int lane = tid & 31;
    const int bm = blockIdx.y * 128;
    const int bn = blockIdx.x * 128;
    const int wm = (wid & 3) * 32;        // warp row offset
    const int wn = (wid >> 2) * 64;       // warp col offset

    const uint32_t uAh = smem_u32(sAh);
    const uint32_t uAl = smem_u32(sAl);
    const uint32_t uBh = smem_u32(sBh);
    const uint32_t uBl = smem_u32(sBl);

    float acc[2][8][4];
#pragma unroll
    for (int i = 0; i < 2; i++)
#pragma unroll
        for (int j = 0; j < 8; j++)
#pragma unroll
            for (int k = 0; k < 4; k++) acc[i][j][k] = 0.0f;

    const uint4 zero4 = make_uint4(0, 0, 0, 0);
    // fixed per-thread column slots within the 32-wide K chunk
    const int a_c = (tid & 7) * 4;        // A: float4 granularity
    const int a_r0 = tid >> 3;            // rows a_r0 + 32*j
    const int b_c = (tid & 3) * 8;        // B: uint4 (8 halves)
    const int b_r0 = tid >> 2;            // rows b_r0 + 64*j

    for (int k0 = 0; k0 < DIM; k0 += 32) {
        // ---- stage A: build bf16 hi/lo in smem from fp32 source ----
#pragma unroll
        for (int j = 0; j < 4; j++) {
            int row = a_r0 + j * 32;
            int grow = bm + row;
            float4 v = make_float4(0.f, 0.f, 0.f, 0.f);
            if (grow < M) {
                if (MODE == 0) {
                    v = *reinterpret_cast<const float4*>(Asrc + grow * DIM + k0 + a_c);
                } else {
                    int r = grow / NTS;
                    int t = grow - r * NTS;
                    float4 rv = *reinterpret_cast<const float4*>(&d_relpart[r * DIM + k0 + a_c]);
                    float4 tv = *reinterpret_cast<const float4*>(&d_timepart[t * DIM + k0 + a_c]);
                    float4 bv = *reinterpret_cast<const float4*>(&b_rt[k0 + a_c]);
                    v.x = lrelu(rv.x + tv.x + bv.x);
                    v.y = lrelu(rv.y + tv.y + bv.y);
                    v.z = lrelu(rv.z + tv.z + bv.z);
                    v.w = lrelu(rv.w + tv.w + bv.w);
                }
            }
            __nv_bfloat16 h[4], l[4];
            bf16_split(v.x, h[0], l[0]); bf16_split(v.y, h[1], l[1]);
            bf16_split(v.z, h[2], l[2]); bf16_split(v.w, h[3], l[3]);
            __nv_bfloat16* ph = &sAh[row * PITCH + a_c];
            __nv_bfloat16* pl = &sAl[row * PITCH + a_c];
            *reinterpret_cast<__nv_bfloat162*>(ph)     = __nv_bfloat162(h[0], h[1]);
            *reinterpret_cast<__nv_bfloat162*>(ph + 2) = __nv_bfloat162(h[2], h[3]);
            *reinterpret_cast<__nv_bfloat162*>(pl)     = __nv_bfloat162(l[0], l[1]);
            *reinterpret_cast<__nv_bfloat162*>(pl + 2) = __nv_bfloat162(l[2], l[3]);
        }
        // ---- stage B: copy preprocessed bf16 hi/lo weights ----
#pragma unroll
        for (int j = 0; j < 2; j++) {
            int row = b_r0 + j * 64;
            uint4 wh = *reinterpret_cast<const uint4*>(Bhi + (bn + row) * DIM + k0 + b_c);
            uint4 wl = *reinterpret_cast<const uint4*>(Blo + (bn + row) * DIM + k0 + b_c);
            *reinterpret_cast<uint4*>(&sBh[row * PITCH + b_c]) = wh;
            *reinterpret_cast<uint4*>(&sBl[row * PITCH + b_c]) = wl;
        }
        __syncthreads();

#pragma unroll
        for (int ks = 0; ks < 2; ks++) {
            // A fragments for 2 m-tiles (hi & lo)
            uint32_t ah[2][4], al[2][4];
#pragma unroll
            for (int mt = 0; mt < 2; mt++) {
                int row = wm + mt * 16 + (lane & 15);
                int koff = ks * 16 + ((lane >> 4) << 3);
                uint32_t off = (uint32_t)(row * PITCH + koff) * 2;
                ldsm4(ah[mt], uAh + off);
                ldsm4(al[mt], uAl + off);
            }
            // B fragments: 4 pairs of n-tiles
#pragma unroll
            for (int np = 0; np < 4; np++) {
                int mat = lane >> 3;
                int row = wn + np * 16 + ((mat >> 1) << 3) + (lane & 7);
                int koff = ks * 16 + ((mat & 1) << 3);
                uint32_t off = (uint32_t)(row * PITCH + koff) * 2;
                uint32_t bh[4], bl[4];
                ldsm4(bh, uBh + off);
                ldsm4(bl, uBl + off);
#pragma unroll
                for (int mt = 0; mt < 2; mt++) {
                    mma_bf16(acc[mt][np * 2],     ah[mt], &bh[0]);
                    mma_bf16(acc[mt][np * 2],     ah[mt], &bl[0]);
                    mma_bf16(acc[mt][np * 2],     al[mt], &bh[0]);
                    mma_bf16(acc[mt][np * 2 + 1], ah[mt], &bh[2]);
                    mma_bf16(acc[mt][np * 2 + 1], ah[mt], &bl[2]);
                    mma_bf16(acc[mt][np * 2 + 1], al[mt], &bh[2]);
                }
            }
        }
        __syncthreads();
    }

    // epilogue: direct float2 stores
    const int tr = lane >> 2;
    const int tc = (lane & 3) * 2;
#pragma unroll
    for (int mt = 0; mt < 2; mt++) {
        int grow0 = bm + wm + mt * 16 + tr;
        int grow1 = grow0 + 8;
#pragma unroll
        for (int nt = 0; nt < 8; nt++) {
            int gcol = bn + wn + nt * 8 + tc;
            if (grow0 < M) {
                float2 v0 = make_float2(acc[mt][nt][0], acc[mt][nt][1]);
                *reinterpret_cast<float2*>(&C[grow0 * ldc + gcol]) = v0;
            }
            if (grow1 < M) {
                float2 v1 = make_float2(acc[mt][nt][2], acc[mt][nt][3]);
                *reinterpret_cast<float2*>(&C[grow1 * ldc + gcol]) = v1;
            }
        }
    }
}

// ---------------- counting sort by dst -----------------------------
__global__ void k_count(const int* __restrict__ edges) {
    int e = blockIdx.x * blockDim.x + threadIdx.x;
    if (e >= NEDGES) return;
    int4 ed = reinterpret_cast<const int4*>(edges)[e];
    atomicAdd(&d_counts[ed.y], 1);
}

__global__ __launch_bounds__(1024) void k_scan() {
    __shared__ int wsum[32];
    const int CH = 49;                      // 1024*49 = 50176 >= 50000
    int t = threadIdx.x;
    int base = t * CH;
    int s = 0;
    for (int i = 0; i < CH; i++) {
        int j = base + i;
        if (j < NNODES) s += d_counts[j];
    }
    int lane = t & 31, w = t >> 5;
    int v = s;
#pragma unroll
    for (int o = 1; o < 32; o <<= 1) {
        int u = __shfl_up_sync(0xFFFFFFFFu, v, o);
        if (lane >= o) v += u;
    }
    if (lane == 31) wsum[w] = v;
    __syncthreads();
    if (w == 0) {
        int x2 = wsum[lane];
#pragma unroll
        for (int o = 1; o < 32; o <<= 1) {
            int u = __shfl_up_sync(0xFFFFFFFFu, x2, o);
            if (lane >= o) x2 += u;
        }
        wsum[lane] = x2;
    }
    __syncthreads();
    int excl = v - s + (w > 0 ? wsum[w - 1] : 0);
    int run = excl;
    for (int i = 0; i < CH; i++) {
        int j = base + i;
        if (j < NNODES) {
            d_offsets[j] = run;
            d_cursor[j] = run;
            run += d_counts[j];
        }
    }
    if (t == 1023) d_offsets[NNODES] = run;
}

__global__ void k_scatter(const int* __restrict__ edges) {
    int e = blockIdx.x * blockDim.x + threadIdx.x;
    if (e >= NEDGES) return;
    int4 ed = reinterpret_cast<const int4*>(edges)[e];
    int pos = atomicAdd(&d_cursor[ed.y], 1);
    d_ssrc[pos] = ed.x;
    d_spair[pos] = ed.z * NTS + ed.w;
}

// ---------------- aggregation: warp per node, no atomics -----------
__global__ __launch_bounds__(256) void k_agg(float* __restrict__ out,
                                             const float* __restrict__ b_fc) {
    int warp = (blockIdx.x * blockDim.x + threadIdx.x) >> 5;
    int lane = threadIdx.x & 31;
    if (warp >= NNODES) return;

    int s0 = d_offsets[warp];
    int s1 = d_offsets[warp + 1];

    const float4* P4 = reinterpret_cast<const float4*>(d_P);
    const float4* R4 = reinterpret_cast<const float4*>(d_rtb);

    float4 bias4 = reinterpret_cast<const float4*>(b_fc)[lane];
    float4 c3 = P4[warp * 64 + 32 + lane];
    c3.x += bias4.x; c3.y += bias4.y; c3.z += bias4.z; c3.w += bias4.w;

    float ax = 0.f, ay = 0.f, az = 0.f, aw = 0.f;
    for (int i = s0; i < s1; i++) {
        int s = __ldg(&d_ssrc[i]);
        int pr = __ldg(&d_spair[i]);
        float4 a = __ldg(&P4[s * 64 + lane]);
        float4 b = __ldg(&R4[pr * 32 + lane]);
        ax += lrelu(a.x + b.x + c3.x);
        ay += lrelu(a.y + b.y + c3.y);
        az += lrelu(a.z + b.z + c3.z);
        aw += lrelu(a.w + b.w + c3.w);
    }
    int cnt = s1 - s0;
    float inv = 1.0f / (float)(cnt > 0 ? cnt : 1);
    float4 r;
    r.x = ax * inv; r.y = ay * inv; r.z = az * inv; r.w = aw * inv;
    reinterpret_cast<float4*>(out)[warp * 32 + lane] = r;
}

// ---------------- launcher ----------------------------------------
extern "C" void kernel_launch(void* const* d_in, const int* in_sizes, int n_in,
                              void* d_out, int out_size) {
    const float* x          = (const float*)d_in[0];
    const float* rel_table  = (const float*)d_in[1];
    const float* time_table = (const float*)d_in[2];
    const float* W_rt       = (const float*)d_in[3];
    const float* b_rt       = (const float*)d_in[4];
    const float* W_fc       = (const float*)d_in[5];
    const float* b_fc       = (const float*)d_in[6];
    const int*   edges      = (const int*)d_in[7];
    float* out = (float*)d_out;

    void *pP, *pRtb, *pBh, *pBl, *pW2h, *pW2l, *pCounts;
    cudaGetSymbolAddress(&pP, d_P);
    cudaGetSymbolAddress(&pRtb, d_rtb);
    cudaGetSymbolAddress(&pBh, d_bT_hi);
    cudaGetSymbolAddress(&pBl, d_bT_lo);
    cudaGetSymbolAddress(&pW2h, d_w2T_hi);
    cudaGetSymbolAddress(&pW2l, d_w2T_lo);
    cudaGetSymbolAddress(&pCounts, d_counts);

    // prep: projections + weight transposes (sort chain interleaved, independent)
    cudaMemsetAsync(pCounts, 0, NNODES * sizeof(int));
    k_proj<<<NREL + NTS, DIM>>>(rel_table, time_table, W_rt);
    k_wT<<<(3 * DIM * DIM + 255) / 256, 256>>>(W_fc);
    k_count<<<(NEDGES + 255) / 256, 256>>>(edges);

    // P = x @ [W1 | W3]   (HMMA bf16x3, split fused into staging)
    {
        dim3 grid(2, (NNODES + 127) / 128);
        hmma_fused<0><<<grid, 256>>>(
            x, (const __nv_bfloat16*)pBh, (const __nv_bfloat16*)pBl,
            nullptr, (float*)pP, NNODES, 2 * DIM);
    }
    // rtb = lrelu(relpart+timepart+b_rt) @ W2   (V fused into staging)
    {
        dim3 grid(1, (NPAIR + 127) / 128);
        hmma_fused<1><<<grid, 256>>>(
            nullptr, (const __nv_bfloat16*)pW2h, (const __nv_bfloat16*)pW2l,
            b_rt, (float*)pRtb, NPAIR, DIM);
    }

    // finish counting sort of edges by dst
    k_scan<<<1, 1024>>>();
    k_scatter<<<(NEDGES + 255) / 256, 256>>>(edges);

    // aggregation (fuses bias + lrelu + mean)
    k_agg<<<(NNODES * 32 + 255) / 256, 256>>>(out, b_fc);
}

// round 9
// speedup vs baseline: 1.6741x; 1.0438x over previous
#include <cuda_runtime.h>
#include <cuda_bf16.h>
#include <cstdint>

// ---------------- problem constants (fixed shapes) ----------------
#define NNODES 50000
#define NEDGES 400000
#define HID    64
#define NREL   230
#define NTS    365
#define NPAIR  (NREL * NTS)      // 83950
#define DIM    128               // 2*HID
#define SLOPE  0.2f

#define NB0 782                  // 2 * ceil(50000/128) mode-0 CTAs
#define NB1 657                  // ceil(83950/128)     mode-1 CTAs

// ---------------- device scratch (static; no runtime alloc) -------
__device__ __align__(16) float d_relpart[NREL * DIM];
__device__ __align__(16) float d_timepart[NTS * DIM];
__device__ __align__(16) float d_P[NNODES * 2 * DIM];     // [x@W1 | x@W3], row stride 256
__device__ __align__(16) float d_rtb[NPAIR * DIM];        // V @ W2 (no bias)
__device__ __align__(16) __nv_bfloat16 d_bT_hi[2 * DIM * DIM];   // [W1|W3]^T : [256][128]
__device__ __align__(16) __nv_bfloat16 d_bT_lo[2 * DIM * DIM];
__device__ __align__(16) __nv_bfloat16 d_w2T_hi[DIM * DIM];      // W2^T : [128][128]
__device__ __align__(16) __nv_bfloat16 d_w2T_lo[DIM * DIM];
__device__ int d_counts[NNODES];
__device__ int d_offsets[NNODES + 1];
__device__ int d_cursor[NNODES];
__device__ int d_ssrc[NEDGES];
__device__ int d_spair[NEDGES];

__device__ __forceinline__ float lrelu(float v) {
    return v >= 0.0f ? v : SLOPE * v;
}

__device__ __forceinline__ uint32_t smem_u32(const void* p) {
    uint32_t a;
    asm("{ .reg .u64 t; cvta.to.shared.u64 t, %1; cvt.u32.u64 %0, t; }"
        : "=r"(a) : "l"(p));
    return a;
}

__device__ __forceinline__ void ldsm4(uint32_t* r, uint32_t addr) {
    asm volatile("ldmatrix.sync.aligned.m8n8.x4.shared.b16 {%0,%1,%2,%3}, [%4];"
                 : "=r"(r[0]), "=r"(r[1]), "=r"(r[2]), "=r"(r[3]) : "r"(addr));
}

__device__ __forceinline__ void mma_bf16(float* d, const uint32_t* a, const uint32_t* b) {
    asm volatile(
        "mma.sync.aligned.m16n8k16.row.col.f32.bf16.bf16.f32 "
        "{%0,%1,%2,%3}, {%4,%5,%6,%7}, {%8,%9}, {%0,%1,%2,%3};"
        : "+f"(d[0]), "+f"(d[1]), "+f"(d[2]), "+f"(d[3])
        : "r"(a[0]), "r"(a[1]), "r"(a[2]), "r"(a[3]), "r"(b[0]), "r"(b[1]));
}

__device__ __forceinline__ void cpa16(uint32_t dst, const void* src, int srcsize) {
    asm volatile("cp.async.cg.shared.global [%0], [%1], 16, %2;"
                 :: "r"(dst), "l"(src), "r"(srcsize));
}
#define CPA_COMMIT() asm volatile("cp.async.commit_group;" ::: "memory")
#define CPA_WAIT0()  asm volatile("cp.async.wait_group 0;" ::: "memory")

// ---------------- split helpers ------------------------------------
__device__ __forceinline__ void bf16_split(float v, __nv_bfloat16& hi, __nv_bfloat16& lo) {
    hi = __float2bfloat16_rn(v);
    lo = __float2bfloat16_rn(v - __bfloat162float(hi));
}

// ---------------- merged prep: proj + weight transpose/split ------
__global__ void k_prep(const float* __restrict__ rel_table,
                       const float* __restrict__ time_table,
                       const float* __restrict__ W_rt,
                       const float* __restrict__ W_fc) {
    int b = blockIdx.x;
    int tid = threadIdx.x;
    if (b < NREL + NTS) {
        if (tid >= DIM) return;
        int j = tid;
        float acc = 0.0f;
        if (b < NREL) {
            const float* a = rel_table + b * HID;
#pragma unroll
            for (int k = 0; k < HID; k++) acc += a[k] * W_rt[k * DIM + j];
            d_relpart[b * DIM + j] = acc;
        } else {
            int r = b - NREL;
            const float* a = time_table + r * HID;
#pragma unroll
            for (int k = 0; k < HID; k++) acc += a[k] * W_rt[(HID + k) * DIM + j];
            d_timepart[r * DIM + j] = acc;
        }
    } else {
        int idx = (b - (NREL + NTS)) * 256 + tid;
        if (idx < 2 * DIM * DIM) {
            int n = idx >> 7, k = idx & 127;
            float v = (n < DIM) ? W_fc[k * DIM + n]
                                : W_fc[(2 * DIM + k) * DIM + (n - DIM)];
            __nv_bfloat16 h, l; bf16_split(v, h, l);
            d_bT_hi[idx] = h; d_bT_lo[idx] = l;
        } else if (idx < 3 * DIM * DIM) {
            int j = idx - 2 * DIM * DIM;
            int n = j >> 7, k = j & 127;
            float v = W_fc[(DIM + k) * DIM + n];
            __nv_bfloat16 h, l; bf16_split(v, h, l);
            d_w2T_hi[j] = h; d_w2T_lo[j] = l;
        }
    }
}

// ---------------- merged, pipelined HMMA bf16x3 GEMM --------------
// mode0 (bid < NB0):  P[bm:,bn:] = split(x) @ bT^T        (ldc=256)
// mode1:              rtb[bm:,:] = split(V(pair)) @ w2T^T (ldc=128)
// 256 threads = 8 warps; warp tile 32x64; BK=32; cp.async 2-stage on B + Araw.
#define PITCH 40   // halves per smem row (80B): conflict-free ldmatrix, 16B-aligned

// dynamic smem layout (bytes)
#define OFF_AH   0
#define OFF_AL   10240
#define OFF_BH0  20480
#define OFF_BL0  40960
#define OFF_ARAW 61440
#define SM_TOTAL 77824
#define BUFSZ    10240

__global__ __launch_bounds__(256, 2) void hmma_all(
    const float* __restrict__ x,
    const float* __restrict__ b_rt)
{
    extern __shared__ char smem[];
    const uint32_t sbase = smem_u32(smem);
    const uint32_t uAh = sbase + OFF_AH;
    const uint32_t uAl = sbase + OFF_AL;
    const uint32_t uAraw = sbase + OFF_ARAW;

    const int tid = threadIdx.x;
    const int wid = tid >> 5;
    const int lane = tid & 31;
    const int bid = blockIdx.x;

    const bool m0 = (bid < NB0);
    int bm, bn, ldc, M;
    const __nv_bfloat16 *Bh_, *Bl_;
    float* C;
    if (m0) {
        bm = (bid >> 1) * 128; bn = (bid & 1) * 128;
        Bh_ = d_bT_hi; Bl_ = d_bT_lo; C = d_P; ldc = 256; M = NNODES;
    } else {
        int b2 = bid - NB0;
        bm = b2 * 128; bn = 0;
        Bh_ = d_w2T_hi; Bl_ = d_w2T_lo; C = d_rtb; ldc = 128; M = NPAIR;
    }

    const int wm = (wid & 3) * 32;
    const int wn = (wid >> 2) * 64;

    float acc[2][8][4];
#pragma unroll
    for (int i = 0; i < 2; i++)
#pragma unroll
        for (int j = 0; j < 8; j++)
#pragma unroll
            for (int k = 0; k < 4; k++) acc[i][j][k] = 0.0f;

    // per-thread staging slots
    const int a_c = (tid & 7) * 4;        // A convert: float4 cols
    const int a_r0 = tid >> 3;            // rows a_r0 + 32*j
    const int b_c = (tid & 3) * 8;        // B cp.async: 8 halves (16B)
    const int b_r0 = tid >> 2;            // rows b_r0 + 64*j

    // ---- async issue helpers (inlined lambdas) ----
    auto issueB = [&](int k0, int buf) {
        uint32_t dBh = sbase + OFF_BH0 + buf * BUFSZ;
        uint32_t dBl = sbase + OFF_BL0 + buf * BUFSZ;
#pragma unroll
        for (int j = 0; j < 2; j++) {
            int row = b_r0 + j * 64;
            uint32_t so = (uint32_t)(row * PITCH + b_c) * 2;
            const __nv_bfloat16* gh = Bh_ + (bn + row) * DIM + k0 + b_c;
            const __nv_bfloat16* gl = Bl_ + (bn + row) * DIM + k0 + b_c;
            cpa16(dBh + so, gh, 16);
            cpa16(dBl + so, gl, 16);
        }
    };
    auto issueA = [&](int k0) {
        if (!m0) return;                  // mode1 builds A from L2-hot tables
#pragma unroll
        for (int j = 0; j < 4; j++) {
            int u = tid + 256 * j;
            int row = u >> 3;
            int cg = (u & 7) * 4;
            int grow = bm + row;
            int ok = (grow < M) ? 16 : 0;
            int gr = (grow < M) ? grow : (M - 1);
            cpa16(uAraw + (uint32_t)(row * 32 + cg) * 4,
                  x + (size_t)gr * DIM + k0 + cg, ok);
        }
    };

    // prologue: chunk 0 in flight
    issueA(0);
    issueB(0, 0);
    CPA_COMMIT();

    for (int i = 0; i < 4; i++) {
        const int k0 = i * 32;
        CPA_WAIT0();
        __syncthreads();

        // ---- convert phase: build Ah/Al for chunk i ----
#pragma unroll
        for (int j = 0; j < 4; j++) {
            int row = a_r0 + j * 32;
            float4 v;
            if (m0) {
                v = *reinterpret_cast<const float4*>(
                        smem + OFF_ARAW + (size_t)(row * 32 + a_c) * 4);
            } else {
                int grow = bm + row;
                v = make_float4(0.f, 0.f, 0.f, 0.f);
                if (grow < M) {
                    int r = grow / NTS;
                    int t = grow - r * NTS;
                    float4 rv = *reinterpret_cast<const float4*>(&d_relpart[r * DIM + k0 + a_c]);
                    float4 tv = *reinterpret_cast<const float4*>(&d_timepart[t * DIM + k0 + a_c]);
                    float4 bv = *reinterpret_cast<const float4*>(&b_rt[k0 + a_c]);
                    v.x = lrelu(rv.x + tv.x + bv.x);
                    v.y = lrelu(rv.y + tv.y + bv.y);
                    v.z = lrelu(rv.z + tv.z + bv.z);
                    v.w = lrelu(rv.w + tv.w + bv.w);
                }
            }
            __nv_bfloat16 h[4], l[4];
            bf16_split(v.x, h[0], l[0]); bf16_split(v.y, h[1], l[1]);
            bf16_split(v.z, h[2], l[2]); bf16_split(v.w, h[3], l[3]);
            __nv_bfloat16* ph = reinterpret_cast<__nv_bfloat16*>(smem + OFF_AH) + row * PITCH + a_c;
            __nv_bfloat16* pl = reinterpret_cast<__nv_bfloat16*>(smem + OFF_AL) + row * PITCH + a_c;
            *reinterpret_cast<__nv_bfloat162*>(ph)     = __nv_bfloat162(h[0], h[1]);
            *reinterpret_cast<__nv_bfloat162*>(ph + 2) = __nv_bfloat162(h[2], h[3]);
            *reinterpret_cast<__nv_bfloat162*>(pl)     = __nv_bfloat162(l[0], l[1]);
            *reinterpret_cast<__nv_bfloat162*>(pl + 2) = __nv_bfloat162(l[2], l[3]);
        }
        __syncthreads();

        // ---- prefetch next chunk while computing ----
        if (i < 3) {
            issueA(k0 + 32);
            issueB(k0 + 32, (i + 1) & 1);
            CPA_COMMIT();
        }

        const uint32_t uBh = sbase + OFF_BH0 + (i & 1) * BUFSZ;
        const uint32_t uBl = sbase + OFF_BL0 + (i & 1) * BUFSZ;

#pragma unroll
        for (int ks = 0; ks < 2; ks++) {
            uint32_t ah[2][4], al[2][4];
#pragma unroll
            for (int mt = 0; mt < 2; mt++) {
                int row = wm + mt * 16 + (lane & 15);
                int koff = ks * 16 + ((lane >> 4) << 3);
                uint32_t off = (uint32_t)(row * PITCH + koff) * 2;
                ldsm4(ah[mt], uAh + off);
                ldsm4(al[mt], uAl + off);
            }
#pragma unroll
            for (int np = 0; np < 4; np++) {
                int mat = lane >> 3;
                int row = wn + np * 16 + ((mat >> 1) << 3) + (lane & 7);
                int koff = ks * 16 + ((mat & 1) << 3);
                uint32_t off = (uint32_t)(row * PITCH + koff) * 2;
                uint32_t bh[4], bl[4];
                ldsm4(bh, uBh + off);
                ldsm4(bl, uBl + off);
#pragma unroll
                for (int mt = 0; mt < 2; mt++) {
                    mma_bf16(acc[mt][np * 2],     ah[mt], &bh[0]);
                    mma_bf16(acc[mt][np * 2],     ah[mt], &bl[0]);
                    mma_bf16(acc[mt][np * 2],     al[mt], &bh[0]);
                    mma_bf16(acc[mt][np * 2 + 1], ah[mt], &bh[2]);
                    mma_bf16(acc[mt][np * 2 + 1], ah[mt], &bl[2]);
                    mma_bf16(acc[mt][np * 2 + 1], al[mt], &bh[2]);
                }
            }
        }
        __syncthreads();
    }

    // epilogue: direct float2 stores
    const int tr = lane >> 2;
    const int tc = (lane & 3) * 2;
#pragma unroll
    for (int mt = 0; mt < 2; mt++) {
        int grow0 = bm + wm + mt * 16 + tr;
        int grow1 = grow0 + 8;
#pragma unroll
        for (int nt = 0; nt < 8; nt++) {
            int gcol = bn + wn + nt * 8 + tc;
            if (grow0 < M) {
                float2 v0 = make_float2(acc[mt][nt][0], acc[mt][nt][1]);
                *reinterpret_cast<float2*>(&C[(size_t)grow0 * ldc + gcol]) = v0;
            }
            if (grow1 < M) {
                float2 v1 = make_float2(acc[mt][nt][2], acc[mt][nt][3]);
                *reinterpret_cast<float2*>(&C[(size_t)grow1 * ldc + gcol]) = v1;
            }
        }
    }
}

// ---------------- counting sort by dst -----------------------------
__global__ void k_count(const int* __restrict__ edges) {
    int e = blockIdx.x * blockDim.x + threadIdx.x;
    if (e >= NEDGES) return;
    int4 ed = reinterpret_cast<const int4*>(edges)[e];
    atomicAdd(&d_counts[ed.y], 1);
}

__global__ __launch_bounds__(1024) void k_scan() {
    __shared__ int wsum[32];
    const int CH = 49;
    int t = threadIdx.x;
    int base = t * CH;
    int s = 0;
    for (int i = 0; i < CH; i++) {
        int j = base + i;
        if (j < NNODES) s += d_counts[j];
    }
    int lane = t & 31, w = t >> 5;
    int v = s;
#pragma unroll
    for (int o = 1; o < 32; o <<= 1) {
        int u = __shfl_up_sync(0xFFFFFFFFu, v, o);
        if (lane >= o) v += u;
    }
    if (lane == 31) wsum[w] = v;
    __syncthreads();
    if (w == 0) {
        int x2 = wsum[lane];
#pragma unroll
        for (int o = 1; o < 32; o <<= 1) {
            int u = __shfl_up_sync(0xFFFFFFFFu, x2, o);
            if (lane >= o) x2 += u;
        }
        wsum[lane] = x2;
    }
    __syncthreads();
    int excl = v - s + (w > 0 ? wsum[w - 1] : 0);
    int run = excl;
    for (int i = 0; i < CH; i++) {
        int j = base + i;
        if (j < NNODES) {
            d_offsets[j] = run;
            d_cursor[j] = run;
            run += d_counts[j];
        }
    }
    if (t == 1023) d_offsets[NNODES] = run;
}

__global__ void k_scatter(const int* __restrict__ edges) {
    int e = blockIdx.x * blockDim.x + threadIdx.x;
    if (e >= NEDGES) return;
    int4 ed = reinterpret_cast<const int4*>(edges)[e];
    int pos = atomicAdd(&d_cursor[ed.y], 1);
    d_ssrc[pos] = ed.x;
    d_spair[pos] = ed.z * NTS + ed.w;
}

// ---------------- aggregation: warp per node, no atomics -----------
__global__ __launch_bounds__(256) void k_agg(float* __restrict__ out,
                                             const float* __restrict__ b_fc) {
    int warp = (blockIdx.x * blockDim.x + threadIdx.x) >> 5;
    int lane = threadIdx.x & 31;
    if (warp >= NNODES) return;

    int s0 = d_offsets[warp];
    int s1 = d_offsets[warp + 1];

    const float4* P4 = reinterpret_cast<const float4*>(d_P);
    const float4* R4 = reinterpret_cast<const float4*>(d_rtb);

    float4 bias4 = reinterpret_cast<const float4*>(b_fc)[lane];
    float4 c3 = P4[warp * 64 + 32 + lane];
    c3.x += bias4.x; c3.y += bias4.y; c3.z += bias4.z; c3.w += bias4.w;

    float ax = 0.f, ay = 0.f, az = 0.f, aw = 0.f;
    for (int i = s0; i < s1; i++) {
        int s = __ldg(&d_ssrc[i]);
        int pr = __ldg(&d_spair[i]);
        float4 a = __ldg(&P4[s * 64 + lane]);
        float4 b = __ldg(&R4[pr * 32 + lane]);
        ax += lrelu(a.x + b.x + c3.x);
        ay += lrelu(a.y + b.y + c3.y);
        az += lrelu(a.z + b.z + c3.z);
        aw += lrelu(a.w + b.w + c3.w);
    }
    int cnt = s1 - s0;
    float inv = 1.0f / (float)(cnt > 0 ? cnt : 1);
    float4 r;
    r.x = ax * inv; r.y = ay * inv; r.z = az * inv; r.w = aw * inv;
    reinterpret_cast<float4*>(out)[warp * 32 + lane] = r;
}

// ---------------- launcher ----------------------------------------
extern "C" void kernel_launch(void* const* d_in, const int* in_sizes, int n_in,
                              void* d_out, int out_size) {
    const float* x          = (const float*)d_in[0];
    const float* rel_table  = (const float*)d_in[1];
    const float* time_table = (const float*)d_in[2];
    const float* W_rt       = (const float*)d_in[3];
    const float* b_rt       = (const float*)d_in[4];
    const float* W_fc       = (const float*)d_in[5];
    const float* b_fc       = (const float*)d_in[6];
    const int*   edges      = (const int*)d_in[7];
    float* out = (float*)d_out;

    cudaFuncSetAttribute(hmma_all, cudaFuncAttributeMaxDynamicSharedMemorySize, SM_TOTAL);

    void* pCounts;
    cudaGetSymbolAddress(&pCounts, d_counts);
    cudaMemsetAsync(pCounts, 0, NNODES * sizeof(int));

    // prep (proj + weight split) and edge histogram
    k_prep<<<NREL + NTS + 192, 256>>>(rel_table, time_table, W_rt, W_fc);
    k_count<<<(NEDGES + 255) / 256, 256>>>(edges);

    // both GEMMs in one pipelined launch
    hmma_all<<<NB0 + NB1, 256, SM_TOTAL>>>(x, b_rt);

    // finish counting sort of edges by dst
    k_scan<<<1, 1024>>>();
    k_scatter<<<(NEDGES + 255) / 256, 256>>>(edges);

    // aggregation (fuses bias + lrelu + mean)
    k_agg<<<(NNODES * 32 + 255) / 256, 256>>>(out, b_fc);
}

// round 10
// speedup vs baseline: 2.5070x; 1.4976x over previous
#include <cuda_runtime.h>
#include <cuda_bf16.h>
#include <cstdint>

// ---------------- problem constants (fixed shapes) ----------------
#define NNODES 50000
#define NEDGES 400000
#define HID    64
#define NREL   230
#define NTS    365
#define NPAIR  (NREL * NTS)      // 83950
#define DIM    128               // 2*HID
#define SLOPE  0.2f

#define NB0 782                  // 2 * ceil(50000/128) mode-0 CTAs
#define NB1 657                  // ceil(83950/128)     mode-1 CTAs
#define NBLK ((NNODES + 255) / 256)   // 196 scan blocks

// ---------------- device scratch (static; no runtime alloc) -------
__device__ __align__(16) float d_relpart[NREL * DIM];
__device__ __align__(16) float d_timepart[NTS * DIM];
__device__ __align__(16) float d_P[NNODES * 2 * DIM];     // [x@W1 | x@W3], row stride 256
__device__ __align__(16) float d_rtb[NPAIR * DIM];        // V @ W2 (no bias)
__device__ __align__(16) __nv_bfloat16 d_bT_hi[2 * DIM * DIM];   // [W1|W3]^T : [256][128]
__device__ __align__(16) __nv_bfloat16 d_bT_lo[2 * DIM * DIM];
__device__ __align__(16) __nv_bfloat16 d_w2T_hi[DIM * DIM];      // W2^T : [128][128]
__device__ __align__(16) __nv_bfloat16 d_w2T_lo[DIM * DIM];
__device__ int d_counts[NNODES];
__device__ int d_bsums[NBLK];
__device__ int d_offsets[NNODES + 1];
__device__ int d_cursor[NNODES];
__device__ int d_ssrc[NEDGES];
__device__ int d_spair[NEDGES];

__device__ __forceinline__ float lrelu(float v) {
    return v >= 0.0f ? v : SLOPE * v;
}

__device__ __forceinline__ uint32_t smem_u32(const void* p) {
    uint32_t a;
    asm("{ .reg .u64 t; cvta.to.shared.u64 t, %1; cvt.u32.u64 %0, t; }"
        : "=r"(a) : "l"(p));
    return a;
}

__device__ __forceinline__ void ldsm4(uint32_t* r, uint32_t addr) {
    asm volatile("ldmatrix.sync.aligned.m8n8.x4.shared.b16 {%0,%1,%2,%3}, [%4];"
                 : "=r"(r[0]), "=r"(r[1]), "=r"(r[2]), "=r"(r[3]) : "r"(addr));
}

__device__ __forceinline__ void mma_bf16(float* d, const uint32_t* a, const uint32_t* b) {
    asm volatile(
        "mma.sync.aligned.m16n8k16.row.col.f32.bf16.bf16.f32 "
        "{%0,%1,%2,%3}, {%4,%5,%6,%7}, {%8,%9}, {%0,%1,%2,%3};"
        : "+f"(d[0]), "+f"(d[1]), "+f"(d[2]), "+f"(d[3])
        : "r"(a[0]), "r"(a[1]), "r"(a[2]), "r"(a[3]), "r"(b[0]), "r"(b[1]));
}

__device__ __forceinline__ void cpa16(uint32_t dst, const void* src, int srcsize) {
    asm volatile("cp.async.cg.shared.global [%0], [%1], 16, %2;"
                 :: "r"(dst), "l"(src), "r"(srcsize));
}
#define CPA_COMMIT() asm volatile("cp.async.commit_group;" ::: "memory")
#define CPA_WAIT0()  asm volatile("cp.async.wait_group 0;" ::: "memory")

// ---------------- split helpers ------------------------------------
__device__ __forceinline__ void bf16_split(float v, __nv_bfloat16& hi, __nv_bfloat16& lo) {
    hi = __float2bfloat16_rn(v);
    lo = __float2bfloat16_rn(v - __bfloat162float(hi));
}

// ---------------- merged prep: proj + weight transpose/split ------
__global__ void k_prep(const float* __restrict__ rel_table,
                       const float* __restrict__ time_table,
                       const float* __restrict__ W_rt,
                       const float* __restrict__ W_fc) {
    int b = blockIdx.x;
    int tid = threadIdx.x;
    if (b < NREL + NTS) {
        if (tid >= DIM) return;
        int j = tid;
        float acc = 0.0f;
        if (b < NREL) {
            const float* a = rel_table + b * HID;
#pragma unroll
            for (int k = 0; k < HID; k++) acc += a[k] * W_rt[k * DIM + j];
            d_relpart[b * DIM + j] = acc;
        } else {
            int r = b - NREL;
            const float* a = time_table + r * HID;
#pragma unroll
            for (int k = 0; k < HID; k++) acc += a[k] * W_rt[(HID + k) * DIM + j];
            d_timepart[r * DIM + j] = acc;
        }
    } else {
        int idx = (b - (NREL + NTS)) * 256 + tid;
        if (idx < 2 * DIM * DIM) {
            int n = idx >> 7, k = idx & 127;
            float v = (n < DIM) ? W_fc[k * DIM + n]
                                : W_fc[(2 * DIM + k) * DIM + (n - DIM)];
            __nv_bfloat16 h, l; bf16_split(v, h, l);
            d_bT_hi[idx] = h; d_bT_lo[idx] = l;
        } else if (idx < 3 * DIM * DIM) {
            int j = idx - 2 * DIM * DIM;
            int n = j >> 7, k = j & 127;
            float v = W_fc[(DIM + k) * DIM + n];
            __nv_bfloat16 h, l; bf16_split(v, h, l);
            d_w2T_hi[j] = h; d_w2T_lo[j] = l;
        }
    }
}

// ---------------- merged, pipelined HMMA bf16x3 GEMM --------------
#define PITCH 40   // halves per smem row (80B): conflict-free ldmatrix, 16B-aligned

// dynamic smem layout (bytes)
#define OFF_AH   0
#define OFF_AL   10240
#define OFF_BH0  20480
#define OFF_BL0  40960
#define OFF_ARAW 61440
#define SM_TOTAL 77824
#define BUFSZ    10240

__global__ __launch_bounds__(256, 2) void hmma_all(
    const float* __restrict__ x,
    const float* __restrict__ b_rt)
{
    extern __shared__ char smem[];
    const uint32_t sbase = smem_u32(smem);
    const uint32_t uAh = sbase + OFF_AH;
    const uint32_t uAl = sbase + OFF_AL;
    const uint32_t uAraw = sbase + OFF_ARAW;

    const int tid = threadIdx.x;
    const int wid = tid >> 5;
    const int lane = tid & 31;
    const int bid = blockIdx.x;

    const bool m0 = (bid < NB0);
    int bm, bn, ldc, M;
    const __nv_bfloat16 *Bh_, *Bl_;
    float* C;
    if (m0) {
        bm = (bid >> 1) * 128; bn = (bid & 1) * 128;
        Bh_ = d_bT_hi; Bl_ = d_bT_lo; C = d_P; ldc = 256; M = NNODES;
    } else {
        int b2 = bid - NB0;
        bm = b2 * 128; bn = 0;
        Bh_ = d_w2T_hi; Bl_ = d_w2T_lo; C = d_rtb; ldc = 128; M = NPAIR;
    }

    const int wm = (wid & 3) * 32;
    const int wn = (wid >> 2) * 64;

    float acc[2][8][4];
#pragma unroll
    for (int i = 0; i < 2; i++)
#pragma unroll
        for (int j = 0; j < 8; j++)
#pragma unroll
            for (int k = 0; k < 4; k++) acc[i][j][k] = 0.0f;

    const int a_c = (tid & 7) * 4;
    const int a_r0 = tid >> 3;
    const int b_c = (tid & 3) * 8;
    const int b_r0 = tid >> 2;

    auto issueB = [&](int k0, int buf) {
        uint32_t dBh = sbase + OFF_BH0 + buf * BUFSZ;
        uint32_t dBl = sbase + OFF_BL0 + buf * BUFSZ;
#pragma unroll
        for (int j = 0; j < 2; j++) {
            int row = b_r0 + j * 64;
            uint32_t so = (uint32_t)(row * PITCH + b_c) * 2;
            const __nv_bfloat16* gh = Bh_ + (bn + row) * DIM + k0 + b_c;
            const __nv_bfloat16* gl = Bl_ + (bn + row) * DIM + k0 + b_c;
            cpa16(dBh + so, gh, 16);
            cpa16(dBl + so, gl, 16);
        }
    };
    auto issueA = [&](int k0) {
        if (!m0) return;
#pragma unroll
        for (int j = 0; j < 4; j++) {
            int u = tid + 256 * j;
            int row = u >> 3;
            int cg = (u & 7) * 4;
            int grow = bm + row;
            int ok = (grow < M) ? 16 : 0;
            int gr = (grow < M) ? grow : (M - 1);
            cpa16(uAraw + (uint32_t)(row * 32 + cg) * 4,
                  x + (size_t)gr * DIM + k0 + cg, ok);
        }
    };

    issueA(0);
    issueB(0, 0);
    CPA_COMMIT();

    for (int i = 0; i < 4; i++) {
        const int k0 = i * 32;
        CPA_WAIT0();
        __syncthreads();

#pragma unroll
        for (int j = 0; j < 4; j++) {
            int row = a_r0 + j * 32;
            float4 v;
            if (m0) {
                v = *reinterpret_cast<const float4*>(
                        smem + OFF_ARAW + (size_t)(row * 32 + a_c) * 4);
            } else {
                int grow = bm + row;
                v = make_float4(0.f, 0.f, 0.f, 0.f);
                if (grow < M) {
                    int r = grow / NTS;
                    int t = grow - r * NTS;
                    float4 rv = *reinterpret_cast<const float4*>(&d_relpart[r * DIM + k0 + a_c]);
                    float4 tv = *reinterpret_cast<const float4*>(&d_timepart[t * DIM + k0 + a_c]);
                    float4 bv = *reinterpret_cast<const float4*>(&b_rt[k0 + a_c]);
                    v.x = lrelu(rv.x + tv.x + bv.x);
                    v.y = lrelu(rv.y + tv.y + bv.y);
                    v.z = lrelu(rv.z + tv.z + bv.z);
                    v.w = lrelu(rv.w + tv.w + bv.w);
                }
            }
            __nv_bfloat16 h[4], l[4];
            bf16_split(v.x, h[0], l[0]); bf16_split(v.y, h[1], l[1]);
            bf16_split(v.z, h[2], l[2]); bf16_split(v.w, h[3], l[3]);
            __nv_bfloat16* ph = reinterpret_cast<__nv_bfloat16*>(smem + OFF_AH) + row * PITCH + a_c;
            __nv_bfloat16* pl = reinterpret_cast<__nv_bfloat16*>(smem + OFF_AL) + row * PITCH + a_c;
            *reinterpret_cast<__nv_bfloat162*>(ph)     = __nv_bfloat162(h[0], h[1]);
            *reinterpret_cast<__nv_bfloat162*>(ph + 2) = __nv_bfloat162(h[2], h[3]);
            *reinterpret_cast<__nv_bfloat162*>(pl)     = __nv_bfloat162(l[0], l[1]);
            *reinterpret_cast<__nv_bfloat162*>(pl + 2) = __nv_bfloat162(l[2], l[3]);
        }
        __syncthreads();

        if (i < 3) {
            issueA(k0 + 32);
            issueB(k0 + 32, (i + 1) & 1);
            CPA_COMMIT();
        }

        const uint32_t uBh = sbase + OFF_BH0 + (i & 1) * BUFSZ;
        const uint32_t uBl = sbase + OFF_BL0 + (i & 1) * BUFSZ;

#pragma unroll
        for (int ks = 0; ks < 2; ks++) {
            uint32_t ah[2][4], al[2][4];
#pragma unroll
            for (int mt = 0; mt < 2; mt++) {
                int row = wm + mt * 16 + (lane & 15);
                int koff = ks * 16 + ((lane >> 4) << 3);
                uint32_t off = (uint32_t)(row * PITCH + koff) * 2;
                ldsm4(ah[mt], uAh + off);
                ldsm4(al[mt], uAl + off);
            }
#pragma unroll
            for (int np = 0; np < 4; np++) {
                int mat = lane >> 3;
                int row = wn + np * 16 + ((mat >> 1) << 3) + (lane & 7);
                int koff = ks * 16 + ((mat & 1) << 3);
                uint32_t off = (uint32_t)(row * PITCH + koff) * 2;
                uint32_t bh[4], bl[4];
                ldsm4(bh, uBh + off);
                ldsm4(bl, uBl + off);
#pragma unroll
                for (int mt = 0; mt < 2; mt++) {
                    mma_bf16(acc[mt][np * 2],     ah[mt], &bh[0]);
                    mma_bf16(acc[mt][np * 2],     ah[mt], &bl[0]);
                    mma_bf16(acc[mt][np * 2],     al[mt], &bh[0]);
                    mma_bf16(acc[mt][np * 2 + 1], ah[mt], &bh[2]);
                    mma_bf16(acc[mt][np * 2 + 1], ah[mt], &bl[2]);
                    mma_bf16(acc[mt][np * 2 + 1], al[mt], &bh[2]);
                }
            }
        }
        __syncthreads();
    }

    const int tr = lane >> 2;
    const int tc = (lane & 3) * 2;
#pragma unroll
    for (int mt = 0; mt < 2; mt++) {
        int grow0 = bm + wm + mt * 16 + tr;
        int grow1 = grow0 + 8;
#pragma unroll
        for (int nt = 0; nt < 8; nt++) {
            int gcol = bn + wn + nt * 8 + tc;
            if (grow0 < M) {
                float2 v0 = make_float2(acc[mt][nt][0], acc[mt][nt][1]);
                *reinterpret_cast<float2*>(&C[(size_t)grow0 * ldc + gcol]) = v0;
            }
            if (grow1 < M) {
                float2 v1 = make_float2(acc[mt][nt][2], acc[mt][nt][3]);
                *reinterpret_cast<float2*>(&C[(size_t)grow1 * ldc + gcol]) = v1;
            }
        }
    }
}

// ---------------- counting sort by dst -----------------------------
__global__ void k_count(const int* __restrict__ edges) {
    int e = blockIdx.x * blockDim.x + threadIdx.x;
    if (e >= NEDGES) return;
    int4 ed = reinterpret_cast<const int4*>(edges)[e];
    atomicAdd(&d_counts[ed.y], 1);
}

// ---- two-level scan: block sums -> scan sums -> final offsets ----
__global__ __launch_bounds__(256) void k_bsum() {
    int i = blockIdx.x * 256 + threadIdx.x;
    int lane = threadIdx.x & 31, w = threadIdx.x >> 5;
    int v = (i < NNODES) ? d_counts[i] : 0;
#pragma unroll
    for (int o = 16; o > 0; o >>= 1) v += __shfl_down_sync(0xFFFFFFFFu, v, o);
    __shared__ int ws[8];
    if (lane == 0) ws[w] = v;
    __syncthreads();
    if (threadIdx.x == 0) {
        int s = 0;
#pragma unroll
        for (int j = 0; j < 8; j++) s += ws[j];
        d_bsums[blockIdx.x] = s;
    }
}

__global__ __launch_bounds__(256) void k_scanb() {
    int t = threadIdx.x;
    int lane = t & 31, w = t >> 5;
    int v = (t < NBLK) ? d_bsums[t] : 0;
    int inc = v;
#pragma unroll
    for (int o = 1; o < 32; o <<= 1) {
        int u = __shfl_up_sync(0xFFFFFFFFu, inc, o);
        if (lane >= o) inc += u;
    }
    __shared__ int ws[8];
    if (lane == 31) ws[w] = inc;
    __syncthreads();
    if (w == 0 && lane < 8) {
        int s = ws[lane];
#pragma unroll
        for (int o = 1; o < 8; o <<= 1) {
            int u = __shfl_up_sync(0xFFu, s, o);
            if (lane >= o) s += u;
        }
        ws[lane] = s;
    }
    __syncthreads();
    int excl = inc - v + (w > 0 ? ws[w - 1] : 0);
    if (t < NBLK) d_bsums[t] = excl;
}

__global__ __launch_bounds__(256) void k_scanfin() {
    int b = blockIdx.x;
    int i = b * 256 + threadIdx.x;
    int lane = threadIdx.x & 31, w = threadIdx.x >> 5;
    int v = (i < NNODES) ? d_counts[i] : 0;
    int inc = v;
#pragma unroll
    for (int o = 1; o < 32; o <<= 1) {
        int u = __shfl_up_sync(0xFFFFFFFFu, inc, o);
        if (lane >= o) inc += u;
    }
    __shared__ int ws[8];
    if (lane == 31) ws[w] = inc;
    __syncthreads();
    if (w == 0 && lane < 8) {
        int s = ws[lane];
#pragma unroll
        for (int o = 1; o < 8; o <<= 1) {
            int u = __shfl_up_sync(0xFFu, s, o);
            if (lane >= o) s += u;
        }
        ws[lane] = s;
    }
    __syncthreads();
    int excl = inc - v + (w > 0 ? ws[w - 1] : 0) + d_bsums[b];
    if (i < NNODES) {
        d_offsets[i] = excl;
        d_cursor[i] = excl;
        if (i == NNODES - 1) d_offsets[NNODES] = excl + v;
    }
}

__global__ void k_scatter(const int* __restrict__ edges) {
    int e = blockIdx.x * blockDim.x + threadIdx.x;
    if (e >= NEDGES) return;
    int4 ed = reinterpret_cast<const int4*>(edges)[e];
    int pos = atomicAdd(&d_cursor[ed.y], 1);
    d_ssrc[pos] = ed.x;
    d_spair[pos] = ed.z * NTS + ed.w;
}

// ---------------- aggregation: warp per node, no atomics -----------
__global__ __launch_bounds__(256) void k_agg(float* __restrict__ out,
                                             const float* __restrict__ b_fc) {
    int warp = (blockIdx.x * blockDim.x + threadIdx.x) >> 5;
    int lane = threadIdx.x & 31;
    if (warp >= NNODES) return;

    int s0 = d_offsets[warp];
    int s1 = d_offsets[warp + 1];

    const float4* P4 = reinterpret_cast<const float4*>(d_P);
    const float4* R4 = reinterpret_cast<const float4*>(d_rtb);

    float4 bias4 = reinterpret_cast<const float4*>(b_fc)[lane];
    float4 c3 = P4[warp * 64 + 32 + lane];
    c3.x += bias4.x; c3.y += bias4.y; c3.z += bias4.z; c3.w += bias4.w;

    float ax = 0.f, ay = 0.f, az = 0.f, aw = 0.f;
    for (int i = s0; i < s1; i++) {
        int s = __ldg(&d_ssrc[i]);
        int pr = __ldg(&d_spair[i]);
        float4 a = __ldg(&P4[s * 64 + lane]);
        float4 b = __ldg(&R4[pr * 32 + lane]);
        ax += lrelu(a.x + b.x + c3.x);
        ay += lrelu(a.y + b.y + c3.y);
        az += lrelu(a.z + b.z + c3.z);
        aw += lrelu(a.w + b.w + c3.w);
    }
    int cnt = s1 - s0;
    float inv = 1.0f / (float)(cnt > 0 ? cnt : 1);
    float4 r;
    r.x = ax * inv; r.y = ay * inv; r.z = az * inv; r.w = aw * inv;
    reinterpret_cast<float4*>(out)[warp * 32 + lane] = r;
}

// ---------------- launcher ----------------------------------------
extern "C" void kernel_launch(void* const* d_in, const int* in_sizes, int n_in,
                              void* d_out, int out_size) {
    const float* x          = (const float*)d_in[0];
    const float* rel_table  = (const float*)d_in[1];
    const float* time_table = (const float*)d_in[2];
    const float* W_rt       = (const float*)d_in[3];
    const float* b_rt       = (const float*)d_in[4];
    const float* W_fc       = (const float*)d_in[5];
    const float* b_fc       = (const float*)d_in[6];
    const int*   edges      = (const int*)d_in[7];
    float* out = (float*)d_out;

    cudaFuncSetAttribute(hmma_all, cudaFuncAttributeMaxDynamicSharedMemorySize, SM_TOTAL);

    void* pCounts;
    cudaGetSymbolAddress(&pCounts, d_counts);
    cudaMemsetAsync(pCounts, 0, NNODES * sizeof(int));

    // prep (proj + weight split) and edge histogram
    k_prep<<<NREL + NTS + 192, 256>>>(rel_table, time_table, W_rt, W_fc);
    k_count<<<(NEDGES + 255) / 256, 256>>>(edges);

    // both GEMMs in one pipelined launch
    hmma_all<<<NB0 + NB1, 256, SM_TOTAL>>>(x, b_rt);

    // two-level parallel scan of counts -> offsets/cursor
    k_bsum<<<NBLK, 256>>>();
    k_scanb<<<1, 256>>>();
    k_scanfin<<<NBLK, 256>>>();

    // scatter edges into dst-sorted order
    k_scatter<<<(NEDGES + 255) / 256, 256>>>(edges);

    // aggregation (fuses bias + lrelu + mean)
    k_agg<<<(NNODES * 32 + 255) / 256, 256>>>(out, b_fc);
}

// round 11
// speedup vs baseline: 2.8875x; 1.1518x over previous
#include <cuda_runtime.h>
#include <cuda_bf16.h>
#include <cstdint>

// ---------------- problem constants (fixed shapes) ----------------
#define NNODES 50000
#define NEDGES 400000
#define HID    64
#define NREL   230
#define NTS    365
#define NPAIR  (NREL * NTS)      // 83950
#define DIM    128               // 2*HID
#define SLOPE  0.2f

#define NB0 782                  // 2 * ceil(50000/128) mode-0 CTAs
#define NB1 657                  // ceil(83950/128)     mode-1 CTAs
#define NBLK ((NNODES + 255) / 256)   // 196 scan blocks

// ---------------- device scratch (static; no runtime alloc) -------
__device__ __align__(16) float d_relpart[NREL * DIM];
__device__ __align__(16) float d_timepart[NTS * DIM];
__device__ __align__(16) float d_P[NNODES * 2 * DIM];     // [x@W1 | x@W3], row stride 256
__device__ __align__(16) float d_rtb[NPAIR * DIM];        // V @ W2 (no bias)
__device__ __align__(16) __nv_bfloat16 d_bT_hi[2 * DIM * DIM];   // [W1|W3]^T : [256][128]
__device__ __align__(16) __nv_bfloat16 d_bT_lo[2 * DIM * DIM];
__device__ __align__(16) __nv_bfloat16 d_w2T_hi[DIM * DIM];      // W2^T : [128][128]
__device__ __align__(16) __nv_bfloat16 d_w2T_lo[DIM * DIM];
__device__ int d_counts[NNODES];
__device__ int d_bsums[NBLK];
__device__ int d_offsets[NNODES + 1];
__device__ int d_cursor[NNODES];
__device__ int d_ssrc[NEDGES];
__device__ int d_spair[NEDGES];

__device__ __forceinline__ float lrelu(float v) {
    return v >= 0.0f ? v : SLOPE * v;
}

__device__ __forceinline__ uint32_t smem_u32(const void* p) {
    uint32_t a;
    asm("{ .reg .u64 t; cvta.to.shared.u64 t, %1; cvt.u32.u64 %0, t; }"
        : "=r"(a) : "l"(p));
    return a;
}

__device__ __forceinline__ void ldsm4(uint32_t* r, uint32_t addr) {
    asm volatile("ldmatrix.sync.aligned.m8n8.x4.shared.b16 {%0,%1,%2,%3}, [%4];"
                 : "=r"(r[0]), "=r"(r[1]), "=r"(r[2]), "=r"(r[3]) : "r"(addr));
}

__device__ __forceinline__ void mma_bf16(float* d, const uint32_t* a, const uint32_t* b) {
    asm volatile(
        "mma.sync.aligned.m16n8k16.row.col.f32.bf16.bf16.f32 "
        "{%0,%1,%2,%3}, {%4,%5,%6,%7}, {%8,%9}, {%0,%1,%2,%3};"
        : "+f"(d[0]), "+f"(d[1]), "+f"(d[2]), "+f"(d[3])
        : "r"(a[0]), "r"(a[1]), "r"(a[2]), "r"(a[3]), "r"(b[0]), "r"(b[1]));
}

__device__ __forceinline__ void cpa16(uint32_t dst, const void* src, int srcsize) {
    asm volatile("cp.async.cg.shared.global [%0], [%1], 16, %2;"
                 :: "r"(dst), "l"(src), "r"(srcsize));
}
#define CPA_COMMIT() asm volatile("cp.async.commit_group;" ::: "memory")
#define CPA_WAIT0()  asm volatile("cp.async.wait_group 0;" ::: "memory")

// ---------------- split helpers ------------------------------------
__device__ __forceinline__ void bf16_split(float v, __nv_bfloat16& hi, __nv_bfloat16& lo) {
    hi = __float2bfloat16_rn(v);
    lo = __float2bfloat16_rn(v - __bfloat162float(hi));
}

// ---------------- merged prep: proj + weight transpose/split ------
__global__ void k_prep(const float* __restrict__ rel_table,
                       const float* __restrict__ time_table,
                       const float* __restrict__ W_rt,
                       const float* __restrict__ W_fc) {
    int b = blockIdx.x;
    int tid = threadIdx.x;
    if (b < NREL + NTS) {
        if (tid >= DIM) return;
        int j = tid;
        float acc = 0.0f;
        if (b < NREL) {
            const float* a = rel_table + b * HID;
#pragma unroll
            for (int k = 0; k < HID; k++) acc += a[k] * W_rt[k * DIM + j];
            d_relpart[b * DIM + j] = acc;
        } else {
            int r = b - NREL;
            const float* a = time_table + r * HID;
#pragma unroll
            for (int k = 0; k < HID; k++) acc += a[k] * W_rt[(HID + k) * DIM + j];
            d_timepart[r * DIM + j] = acc;
        }
    } else {
        int idx = (b - (NREL + NTS)) * 256 + tid;
        if (idx < 2 * DIM * DIM) {
            int n = idx >> 7, k = idx & 127;
            float v = (n < DIM) ? W_fc[k * DIM + n]
                                : W_fc[(2 * DIM + k) * DIM + (n - DIM)];
            __nv_bfloat16 h, l; bf16_split(v, h, l);
            d_bT_hi[idx] = h; d_bT_lo[idx] = l;
        } else if (idx < 3 * DIM * DIM) {
            int j = idx - 2 * DIM * DIM;
            int n = j >> 7, k = j & 127;
            float v = W_fc[(DIM + k) * DIM + n];
            __nv_bfloat16 h, l; bf16_split(v, h, l);
            d_w2T_hi[j] = h; d_w2T_lo[j] = l;
        }
    }
}

// ---------------- merged, pipelined HMMA bf16x3 GEMM --------------
#define PITCH 40   // halves per smem row (80B): conflict-free ldmatrix, 16B-aligned

// dynamic smem layout (bytes)
#define OFF_AH   0
#define OFF_AL   10240
#define OFF_BH0  20480
#define OFF_BL0  40960
#define OFF_ARAW 61440
#define SM_TOTAL 77824
#define BUFSZ    10240

__global__ __launch_bounds__(256, 2) void hmma_all(
    const float* __restrict__ x,
    const float* __restrict__ b_rt)
{
    extern __shared__ char smem[];
    const uint32_t sbase = smem_u32(smem);
    const uint32_t uAh = sbase + OFF_AH;
    const uint32_t uAl = sbase + OFF_AL;
    const uint32_t uAraw = sbase + OFF_ARAW;

    const int tid = threadIdx.x;
    const int wid = tid >> 5;
    const int lane = tid & 31;
    const int bid = blockIdx.x;

    const bool m0 = (bid < NB0);
    int bm, bn, ldc, M;
    const __nv_bfloat16 *Bh_, *Bl_;
    float* C;
    if (m0) {
        bm = (bid >> 1) * 128; bn = (bid & 1) * 128;
        Bh_ = d_bT_hi; Bl_ = d_bT_lo; C = d_P; ldc = 256; M = NNODES;
    } else {
        int b2 = bid - NB0;
        bm = b2 * 128; bn = 0;
        Bh_ = d_w2T_hi; Bl_ = d_w2T_lo; C = d_rtb; ldc = 128; M = NPAIR;
    }

    const int wm = (wid & 3) * 32;
    const int wn = (wid >> 2) * 64;

    float acc[2][8][4];
#pragma unroll
    for (int i = 0; i < 2; i++)
#pragma unroll
        for (int j = 0; j < 8; j++)
#pragma unroll
            for (int k = 0; k < 4; k++) acc[i][j][k] = 0.0f;

    const int a_c = (tid & 7) * 4;
    const int a_r0 = tid >> 3;
    const int b_c = (tid & 3) * 8;
    const int b_r0 = tid >> 2;

    auto issueB = [&](int k0, int buf) {
        uint32_t dBh = sbase + OFF_BH0 + buf * BUFSZ;
        uint32_t dBl = sbase + OFF_BL0 + buf * BUFSZ;
#pragma unroll
        for (int j = 0; j < 2; j++) {
            int row = b_r0 + j * 64;
            uint32_t so = (uint32_t)(row * PITCH + b_c) * 2;
            const __nv_bfloat16* gh = Bh_ + (bn + row) * DIM + k0 + b_c;
            const __nv_bfloat16* gl = Bl_ + (bn + row) * DIM + k0 + b_c;
            cpa16(dBh + so, gh, 16);
            cpa16(dBl + so, gl, 16);
        }
    };
    auto issueA = [&](int k0) {
        if (!m0) return;
#pragma unroll
        for (int j = 0; j < 4; j++) {
            int u = tid + 256 * j;
            int row = u >> 3;
            int cg = (u & 7) * 4;
            int grow = bm + row;
            int ok = (grow < M) ? 16 : 0;
            int gr = (grow < M) ? grow : (M - 1);
            cpa16(uAraw + (uint32_t)(row * 32 + cg) * 4,
                  x + (size_t)gr * DIM + k0 + cg, ok);
        }
    };

    issueA(0);
    issueB(0, 0);
    CPA_COMMIT();

    for (int i = 0; i < 4; i++) {
        const int k0 = i * 32;
        CPA_WAIT0();
        __syncthreads();

#pragma unroll
        for (int j = 0; j < 4; j++) {
            int row = a_r0 + j * 32;
            float4 v;
            if (m0) {
                v = *reinterpret_cast<const float4*>(
                        smem + OFF_ARAW + (size_t)(row * 32 + a_c) * 4);
            } else {
                int grow = bm + row;
                v = make_float4(0.f, 0.f, 0.f, 0.f);
                if (grow < M) {
                    int r = grow / NTS;
                    int t = grow - r * NTS;
                    float4 rv = *reinterpret_cast<const float4*>(&d_relpart[r * DIM + k0 + a_c]);
                    float4 tv = *reinterpret_cast<const float4*>(&d_timepart[t * DIM + k0 + a_c]);
                    float4 bv = *reinterpret_cast<const float4*>(&b_rt[k0 + a_c]);
                    v.x = lrelu(rv.x + tv.x + bv.x);
                    v.y = lrelu(rv.y + tv.y + bv.y);
                    v.z = lrelu(rv.z + tv.z + bv.z);
                    v.w = lrelu(rv.w + tv.w + bv.w);
                }
            }
            __nv_bfloat16 h[4], l[4];
            bf16_split(v.x, h[0], l[0]); bf16_split(v.y, h[1], l[1]);
            bf16_split(v.z, h[2], l[2]); bf16_split(v.w, h[3], l[3]);
            __nv_bfloat16* ph = reinterpret_cast<__nv_bfloat16*>(smem + OFF_AH) + row * PITCH + a_c;
            __nv_bfloat16* pl = reinterpret_cast<__nv_bfloat16*>(smem + OFF_AL) + row * PITCH + a_c;
            *reinterpret_cast<__nv_bfloat162*>(ph)     = __nv_bfloat162(h[0], h[1]);
            *reinterpret_cast<__nv_bfloat162*>(ph + 2) = __nv_bfloat162(h[2], h[3]);
            *reinterpret_cast<__nv_bfloat162*>(pl)     = __nv_bfloat162(l[0], l[1]);
            *reinterpret_cast<__nv_bfloat162*>(pl + 2) = __nv_bfloat162(l[2], l[3]);
        }
        __syncthreads();

        if (i < 3) {
            issueA(k0 + 32);
            issueB(k0 + 32, (i + 1) & 1);
            CPA_COMMIT();
        }

        const uint32_t uBh = sbase + OFF_BH0 + (i & 1) * BUFSZ;
        const uint32_t uBl = sbase + OFF_BL0 + (i & 1) * BUFSZ;

#pragma unroll
        for (int ks = 0; ks < 2; ks++) {
            uint32_t ah[2][4], al[2][4];
#pragma unroll
            for (int mt = 0; mt < 2; mt++) {
                int row = wm + mt * 16 + (lane & 15);
                int koff = ks * 16 + ((lane >> 4) << 3);
                uint32_t off = (uint32_t)(row * PITCH + koff) * 2;
                ldsm4(ah[mt], uAh + off);
                ldsm4(al[mt], uAl + off);
            }
#pragma unroll
            for (int np = 0; np < 4; np++) {
                int mat = lane >> 3;
                int row = wn + np * 16 + ((mat >> 1) << 3) + (lane & 7);
                int koff = ks * 16 + ((mat & 1) << 3);
                uint32_t off = (uint32_t)(row * PITCH + koff) * 2;
                uint32_t bh[4], bl[4];
                ldsm4(bh, uBh + off);
                ldsm4(bl, uBl + off);
#pragma unroll
                for (int mt = 0; mt < 2; mt++) {
                    mma_bf16(acc[mt][np * 2],     ah[mt], &bh[0]);
                    mma_bf16(acc[mt][np * 2],     ah[mt], &bl[0]);
                    mma_bf16(acc[mt][np * 2],     al[mt], &bh[0]);
                    mma_bf16(acc[mt][np * 2 + 1], ah[mt], &bh[2]);
                    mma_bf16(acc[mt][np * 2 + 1], ah[mt], &bl[2]);
                    mma_bf16(acc[mt][np * 2 + 1], al[mt], &bh[2]);
                }
            }
        }
        __syncthreads();
    }

    const int tr = lane >> 2;
    const int tc = (lane & 3) * 2;
#pragma unroll
    for (int mt = 0; mt < 2; mt++) {
        int grow0 = bm + wm + mt * 16 + tr;
        int grow1 = grow0 + 8;
#pragma unroll
        for (int nt = 0; nt < 8; nt++) {
            int gcol = bn + wn + nt * 8 + tc;
            if (grow0 < M) {
                float2 v0 = make_float2(acc[mt][nt][0], acc[mt][nt][1]);
                *reinterpret_cast<float2*>(&C[(size_t)grow0 * ldc + gcol]) = v0;
            }
            if (grow1 < M) {
                float2 v1 = make_float2(acc[mt][nt][2], acc[mt][nt][3]);
                *reinterpret_cast<float2*>(&C[(size_t)grow1 * ldc + gcol]) = v1;
            }
        }
    }
}

// ---------------- counting sort by dst -----------------------------
__global__ void k_count(const int* __restrict__ edges) {
    int e = blockIdx.x * blockDim.x + threadIdx.x;
    if (e >= NEDGES) return;
    int4 ed = reinterpret_cast<const int4*>(edges)[e];
    atomicAdd(&d_counts[ed.y], 1);
}

// ---- two-level scan: block sums -> scan sums -> final offsets ----
__global__ __launch_bounds__(256) void k_bsum() {
    int i = blockIdx.x * 256 + threadIdx.x;
    int lane = threadIdx.x & 31, w = threadIdx.x >> 5;
    int v = (i < NNODES) ? d_counts[i] : 0;
#pragma unroll
    for (int o = 16; o > 0; o >>= 1) v += __shfl_down_sync(0xFFFFFFFFu, v, o);
    __shared__ int ws[8];
    if (lane == 0) ws[w] = v;
    __syncthreads();
    if (threadIdx.x == 0) {
        int s = 0;
#pragma unroll
        for (int j = 0; j < 8; j++) s += ws[j];
        d_bsums[blockIdx.x] = s;
    }
}

__global__ __launch_bounds__(256) void k_scanb() {
    int t = threadIdx.x;
    int lane = t & 31, w = t >> 5;
    int v = (t < NBLK) ? d_bsums[t] : 0;
    int inc = v;
#pragma unroll
    for (int o = 1; o < 32; o <<= 1) {
        int u = __shfl_up_sync(0xFFFFFFFFu, inc, o);
        if (lane >= o) inc += u;
    }
    __shared__ int ws[8];
    if (lane == 31) ws[w] = inc;
    __syncthreads();
    if (w == 0 && lane < 8) {
        int s = ws[lane];
#pragma unroll
        for (int o = 1; o < 8; o <<= 1) {
            int u = __shfl_up_sync(0xFFu, s, o);
            if (lane >= o) s += u;
        }
        ws[lane] = s;
    }
    __syncthreads();
    int excl = inc - v + (w > 0 ? ws[w - 1] : 0);
    if (t < NBLK) d_bsums[t] = excl;
}

__global__ __launch_bounds__(256) void k_scanfin() {
    int b = blockIdx.x;
    int i = b * 256 + threadIdx.x;
    int lane = threadIdx.x & 31, w = threadIdx.x >> 5;
    int v = (i < NNODES) ? d_counts[i] : 0;
    int inc = v;
#pragma unroll
    for (int o = 1; o < 32; o <<= 1) {
        int u = __shfl_up_sync(0xFFFFFFFFu, inc, o);
        if (lane >= o) inc += u;
    }
    __shared__ int ws[8];
    if (lane == 31) ws[w] = inc;
    __syncthreads();
    if (w == 0 && lane < 8) {
        int s = ws[lane];
#pragma unroll
        for (int o = 1; o < 8; o <<= 1) {
            int u = __shfl_up_sync(0xFFu, s, o);
            if (lane >= o) s += u;
        }
        ws[lane] = s;
    }
    __syncthreads();
    int excl = inc - v + (w > 0 ? ws[w - 1] : 0) + d_bsums[b];
    if (i < NNODES) {
        d_offsets[i] = excl;
        d_cursor[i] = excl;
        if (i == NNODES - 1) d_offsets[NNODES] = excl + v;
    }
}

__global__ void k_scatter(const int* __restrict__ edges) {
    int e = blockIdx.x * blockDim.x + threadIdx.x;
    if (e >= NEDGES) return;
    int4 ed = reinterpret_cast<const int4*>(edges)[e];
    int pos = atomicAdd(&d_cursor[ed.y], 1);
    d_ssrc[pos] = ed.x;
    d_spair[pos] = ed.z * NTS + ed.w;
}

// ---------------- aggregation: warp per node, unroll x2 -----------
__global__ __launch_bounds__(256) void k_agg(float* __restrict__ out,
                                             const float* __restrict__ b_fc) {
    int warp = (blockIdx.x * blockDim.x + threadIdx.x) >> 5;
    int lane = threadIdx.x & 31;
    if (warp >= NNODES) return;

    int s0 = d_offsets[warp];
    int s1 = d_offsets[warp + 1];

    const float4* P4 = reinterpret_cast<const float4*>(d_P);
    const float4* R4 = reinterpret_cast<const float4*>(d_rtb);

    float4 bias4 = reinterpret_cast<const float4*>(b_fc)[lane];
    float4 c3 = P4[warp * 64 + 32 + lane];
    c3.x += bias4.x; c3.y += bias4.y; c3.z += bias4.z; c3.w += bias4.w;

    float ax = 0.f, ay = 0.f, az = 0.f, aw = 0.f;
    int i = s0;
    for (; i + 2 <= s1; i += 2) {
        int sA = __ldg(&d_ssrc[i]);
        int sB = __ldg(&d_ssrc[i + 1]);
        int pA = __ldg(&d_spair[i]);
        int pB = __ldg(&d_spair[i + 1]);
        float4 a0 = __ldg(&P4[sA * 64 + lane]);
        float4 b0 = __ldg(&R4[pA * 32 + lane]);
        float4 a1 = __ldg(&P4[sB * 64 + lane]);
        float4 b1 = __ldg(&R4[pB * 32 + lane]);
        ax += lrelu(a0.x + b0.x + c3.x) + lrelu(a1.x + b1.x + c3.x);
        ay += lrelu(a0.y + b0.y + c3.y) + lrelu(a1.y + b1.y + c3.y);
        az += lrelu(a0.z + b0.z + c3.z) + lrelu(a1.z + b1.z + c3.z);
        aw += lrelu(a0.w + b0.w + c3.w) + lrelu(a1.w + b1.w + c3.w);
    }
    if (i < s1) {
        int s = __ldg(&d_ssrc[i]);
        int pr = __ldg(&d_spair[i]);
        float4 a = __ldg(&P4[s * 64 + lane]);
        float4 b = __ldg(&R4[pr * 32 + lane]);
        ax += lrelu(a.x + b.x + c3.x);
        ay += lrelu(a.y + b.y + c3.y);
        az += lrelu(a.z + b.z + c3.z);
        aw += lrelu(a.w + b.w + c3.w);
    }
    int cnt = s1 - s0;
    float inv = 1.0f / (float)(cnt > 0 ? cnt : 1);
    float4 r;
    r.x = ax * inv; r.y = ay * inv; r.z = az * inv; r.w = aw * inv;
    reinterpret_cast<float4*>(out)[warp * 32 + lane] = r;
}

// ---------------- launcher ----------------------------------------
extern "C" void kernel_launch(void* const* d_in, const int* in_sizes, int n_in,
                              void* d_out, int out_size) {
    const float* x          = (const float*)d_in[0];
    const float* rel_table  = (const float*)d_in[1];
    const float* time_table = (const float*)d_in[2];
    const float* W_rt       = (const float*)d_in[3];
    const float* b_rt       = (const float*)d_in[4];
    const float* W_fc       = (const float*)d_in[5];
    const float* b_fc       = (const float*)d_in[6];
    const int*   edges      = (const int*)d_in[7];
    float* out = (float*)d_out;

    cudaFuncSetAttribute(hmma_all, cudaFuncAttributeMaxDynamicSharedMemorySize, SM_TOTAL);

    // side stream + fork/join events (created once, before first capture)
    static cudaStream_t s1 = nullptr;
    static cudaEvent_t evFork = nullptr, evJoin = nullptr;
    if (!s1) {
        cudaStreamCreateWithFlags(&s1, cudaStreamNonBlocking);
        cudaEventCreateWithFlags(&evFork, cudaEventDisableTiming);
        cudaEventCreateWithFlags(&evJoin, cudaEventDisableTiming);
    }

    void* pCounts;
    cudaGetSymbolAddress(&pCounts, d_counts);

    // ---- fork: sort chain on side stream, GEMM chain on main ----
    cudaEventRecord(evFork, 0);
    cudaStreamWaitEvent(s1, evFork, 0);

    cudaMemsetAsync(pCounts, 0, NNODES * sizeof(int), s1);
    k_count<<<(NEDGES + 255) / 256, 256, 0, s1>>>(edges);
    k_bsum<<<NBLK, 256, 0, s1>>>();
    k_scanb<<<1, 256, 0, s1>>>();
    k_scanfin<<<NBLK, 256, 0, s1>>>();
    k_scatter<<<(NEDGES + 255) / 256, 256, 0, s1>>>(edges);
    cudaEventRecord(evJoin, s1);

    // main stream: prep + both GEMMs
    k_prep<<<NREL + NTS + 192, 256>>>(rel_table, time_table, W_rt, W_fc);
    hmma_all<<<NB0 + NB1, 256, SM_TOTAL>>>(x, b_rt);

    // ---- join: aggregation needs both chains ----
    cudaStreamWaitEvent(0, evJoin, 0);
    k_agg<<<(NNODES * 32 + 255) / 256, 256>>>(out, b_fc);
}

// round 13
// speedup vs baseline: 2.9992x; 1.0387x over previous
#include <cuda_runtime.h>
#include <cuda_bf16.h>
#include <cuda_fp16.h>
#include <cstdint>

// ---------------- problem constants (fixed shapes) ----------------
#define NNODES 50000
#define NEDGES 400000
#define HID    64
#define NREL   230
#define NTS    365
#define NPAIR  (NREL * NTS)      // 83950
#define DIM    128               // 2*HID
#define SLOPE  0.2f

#define NB0 782                  // 2 * ceil(50000/128) mode-0 CTAs
#define NB1 657                  // ceil(83950/128)     mode-1 CTAs
#define NBLK ((NNODES + 255) / 256)   // 196 scan blocks

// ---------------- device scratch (static; no runtime alloc) -------
__device__ __align__(16) float d_relpart[NREL * DIM];
__device__ __align__(16) float d_timepart[NTS * DIM];
__device__ __align__(16) __half d_P1h[NNODES * DIM];      // x@W1 (fp16, gathered per edge)
__device__ __align__(16) float  d_P3[NNODES * DIM];       // x@W3 (fp32, once per node)
__device__ __align__(16) __half d_rtbh[NPAIR * DIM];      // V@W2 (fp16, gathered per edge)
__device__ __align__(16) __nv_bfloat16 d_bT_hi[2 * DIM * DIM];   // [W1|W3]^T : [256][128]
__device__ __align__(16) __nv_bfloat16 d_bT_lo[2 * DIM * DIM];
__device__ __align__(16) __nv_bfloat16 d_w2T_hi[DIM * DIM];      // W2^T : [128][128]
__device__ __align__(16) __nv_bfloat16 d_w2T_lo[DIM * DIM];
__device__ int d_counts[NNODES];
__device__ int d_bsums[NBLK];
__device__ int d_offsets[NNODES + 1];
__device__ int d_cursor[NNODES];
__device__ int d_ssrc[NEDGES];
__device__ int d_spair[NEDGES];

__device__ __forceinline__ float lrelu(float v) {
    return v >= 0.0f ? v : SLOPE * v;
}

__device__ __forceinline__ uint32_t smem_u32(const void* p) {
    uint32_t a;
    asm("{ .reg .u64 t; cvta.to.shared.u64 t, %1; cvt.u32.u64 %0, t; }"
        : "=r"(a) : "l"(p));
    return a;
}

__device__ __forceinline__ void ldsm4(uint32_t* r, uint32_t addr) {
    asm volatile("ldmatrix.sync.aligned.m8n8.x4.shared.b16 {%0,%1,%2,%3}, [%4];"
                 : "=r"(r[0]), "=r"(r[1]), "=r"(r[2]), "=r"(r[3]) : "r"(addr));
}

__device__ __forceinline__ void mma_bf16(float* d, const uint32_t* a, const uint32_t* b) {
    asm volatile(
        "mma.sync.aligned.m16n8k16.row.col.f32.bf16.bf16.f32 "
        "{%0,%1,%2,%3}, {%4,%5,%6,%7}, {%8,%9}, {%0,%1,%2,%3};"
        : "+f"(d[0]), "+f"(d[1]), "+f"(d[2]), "+f"(d[3])
        : "r"(a[0]), "r"(a[1]), "r"(a[2]), "r"(a[3]), "r"(b[0]), "r"(b[1]));
}

__device__ __forceinline__ void cpa16(uint32_t dst, const void* src, int srcsize) {
    asm volatile("cp.async.cg.shared.global [%0], [%1], 16, %2;"
                 :: "r"(dst), "l"(src), "r"(srcsize));
}
#define CPA_COMMIT() asm volatile("cp.async.commit_group;" ::: "memory")
#define CPA_WAIT0()  asm volatile("cp.async.wait_group 0;" ::: "memory")

// ---------------- split helpers ------------------------------------
__device__ __forceinline__ void bf16_split(float v, __nv_bfloat16& hi, __nv_bfloat16& lo) {
    hi = __float2bfloat16_rn(v);
    lo = __float2bfloat16_rn(v - __bfloat162float(hi));
}

// ---------------- merged prep: proj + weight transpose/split ------
__global__ void k_prep(const float* __restrict__ rel_table,
                       const float* __restrict__ time_table,
                       const float* __restrict__ W_rt,
                       const float* __restrict__ W_fc) {
    int b = blockIdx.x;
    int tid = threadIdx.x;
    if (b < NREL + NTS) {
        if (tid >= DIM) return;
        int j = tid;
        float acc = 0.0f;
        if (b < NREL) {
            const float* a = rel_table + b * HID;
#pragma unroll
            for (int k = 0; k < HID; k++) acc += a[k] * W_rt[k * DIM + j];
            d_relpart[b * DIM + j] = acc;
        } else {
            int r = b - NREL;
            const float* a = time_table + r * HID;
#pragma unroll
            for (int k = 0; k < HID; k++) acc += a[k] * W_rt[(HID + k) * DIM + j];
            d_timepart[r * DIM + j] = acc;
        }
    } else {
        int idx = (b - (NREL + NTS)) * 256 + tid;
        if (idx < 2 * DIM * DIM) {
            int n = idx >> 7, k = idx & 127;
            float v = (n < DIM) ? W_fc[k * DIM + n]
                                : W_fc[(2 * DIM + k) * DIM + (n - DIM)];
            __nv_bfloat16 h, l; bf16_split(v, h, l);
            d_bT_hi[idx] = h; d_bT_lo[idx] = l;
        } else if (idx < 3 * DIM * DIM) {
            int j = idx - 2 * DIM * DIM;
            int n = j >> 7, k = j & 127;
            float v = W_fc[(DIM + k) * DIM + n];
            __nv_bfloat16 h, l; bf16_split(v, h, l);
            d_w2T_hi[j] = h; d_w2T_lo[j] = l;
        }
    }
}

// ---------------- merged, pipelined HMMA bf16x3 GEMM --------------
#define PITCH 40   // halves per smem row (80B): conflict-free ldmatrix, 16B-aligned

// dynamic smem layout (bytes)
#define OFF_AH   0
#define OFF_AL   10240
#define OFF_BH0  20480
#define OFF_BL0  40960
#define OFF_ARAW 61440
#define SM_TOTAL 77824
#define BUFSZ    10240

__global__ __launch_bounds__(256, 2) void hmma_all(
    const float* __restrict__ x,
    const float* __restrict__ b_rt)
{
    extern __shared__ char smem[];
    const uint32_t sbase = smem_u32(smem);
    const uint32_t uAh = sbase + OFF_AH;
    const uint32_t uAl = sbase + OFF_AL;
    const uint32_t uAraw = sbase + OFF_ARAW;

    const int tid = threadIdx.x;
    const int wid = tid >> 5;
    const int lane = tid & 31;
    const int bid = blockIdx.x;

    const bool m0 = (bid < NB0);
    int bm, bn, M;
    const __nv_bfloat16 *Bh_, *Bl_;
    if (m0) {
        bm = (bid >> 1) * 128; bn = (bid & 1) * 128;
        Bh_ = d_bT_hi; Bl_ = d_bT_lo; M = NNODES;
    } else {
        int b2 = bid - NB0;
        bm = b2 * 128; bn = 0;
        Bh_ = d_w2T_hi; Bl_ = d_w2T_lo; M = NPAIR;
    }

    const int wm = (wid & 3) * 32;
    const int wn = (wid >> 2) * 64;

    float acc[2][8][4];
#pragma unroll
    for (int i = 0; i < 2; i++)
#pragma unroll
        for (int j = 0; j < 8; j++)
#pragma unroll
            for (int k = 0; k < 4; k++) acc[i][j][k] = 0.0f;

    const int a_c = (tid & 7) * 4;
    const int a_r0 = tid >> 3;
    const int b_c = (tid & 3) * 8;
    const int b_r0 = tid >> 2;

    auto issueB = [&](int k0, int buf) {
        uint32_t dBh = sbase + OFF_BH0 + buf * BUFSZ;
        uint32_t dBl = sbase + OFF_BL0 + buf * BUFSZ;
#pragma unroll
        for (int j = 0; j < 2; j++) {
            int row = b_r0 + j * 64;
            uint32_t so = (uint32_t)(row * PITCH + b_c) * 2;
            const __nv_bfloat16* gh = Bh_ + (bn + row) * DIM + k0 + b_c;
            const __nv_bfloat16* gl = Bl_ + (bn + row) * DIM + k0 + b_c;
            cpa16(dBh + so, gh, 16);
            cpa16(dBl + so, gl, 16);
        }
    };
    auto issueA = [&](int k0) {
        if (!m0) return;
#pragma unroll
        for (int j = 0; j < 4; j++) {
            int u = tid + 256 * j;
            int row = u >> 3;
            int cg = (u & 7) * 4;
            int grow = bm + row;
            int ok = (grow < M) ? 16 : 0;
            int gr = (grow < M) ? grow : (M - 1);
            cpa16(uAraw + (uint32_t)(row * 32 + cg) * 4,
                  x + (size_t)gr * DIM + k0 + cg, ok);
        }
    };

    issueA(0);
    issueB(0, 0);
    CPA_COMMIT();

    for (int i = 0; i < 4; i++) {
        const int k0 = i * 32;
        CPA_WAIT0();
        __syncthreads();

#pragma unroll
        for (int j = 0; j < 4; j++) {
            int row = a_r0 + j * 32;
            float4 v;
            if (m0) {
                v = *reinterpret_cast<const float4*>(
                        smem + OFF_ARAW + (size_t)(row * 32 + a_c) * 4);
            } else {
                int grow = bm + row;
                v = make_float4(0.f, 0.f, 0.f, 0.f);
                if (grow < M) {
                    int r = grow / NTS;
                    int t = grow - r * NTS;
                    float4 rv = *reinterpret_cast<const float4*>(&d_relpart[r * DIM + k0 + a_c]);
                    float4 tv = *reinterpret_cast<const float4*>(&d_timepart[t * DIM + k0 + a_c]);
                    float4 bv = *reinterpret_cast<const float4*>(&b_rt[k0 + a_c]);
                    v.x = lrelu(rv.x + tv.x + bv.x);
                    v.y = lrelu(rv.y + tv.y + bv.y);
                    v.z = lrelu(rv.z + tv.z + bv.z);
                    v.w = lrelu(rv.w + tv.w + bv.w);
                }
            }
            __nv_bfloat16 h[4], l[4];
            bf16_split(v.x, h[0], l[0]); bf16_split(v.y, h[1], l[1]);
            bf16_split(v.z, h[2], l[2]); bf16_split(v.w, h[3], l[3]);
            __nv_bfloat16* ph = reinterpret_cast<__nv_bfloat16*>(smem + OFF_AH) + row * PITCH + a_c;
            __nv_bfloat16* pl = reinterpret_cast<__nv_bfloat16*>(smem + OFF_AL) + row * PITCH + a_c;
            *reinterpret_cast<__nv_bfloat162*>(ph)     = __nv_bfloat162(h[0], h[1]);
            *reinterpret_cast<__nv_bfloat162*>(ph + 2) = __nv_bfloat162(h[2], h[3]);
            *reinterpret_cast<__nv_bfloat162*>(pl)     = __nv_bfloat162(l[0], l[1]);
            *reinterpret_cast<__nv_bfloat162*>(pl + 2) = __nv_bfloat162(l[2], l[3]);
        }
        __syncthreads();

        if (i < 3) {
            issueA(k0 + 32);
            issueB(k0 + 32, (i + 1) & 1);
            CPA_COMMIT();
        }

        const uint32_t uBh = sbase + OFF_BH0 + (i & 1) * BUFSZ;
        const uint32_t uBl = sbase + OFF_BL0 + (i & 1) * BUFSZ;

#pragma unroll
        for (int ks = 0; ks < 2; ks++) {
            uint32_t ah[2][4], al[2][4];
#pragma unroll
            for (int mt = 0; mt < 2; mt++) {
                int row = wm + mt * 16 + (lane & 15);
                int koff = ks * 16 + ((lane >> 4) << 3);
                uint32_t off = (uint32_t)(row * PITCH + koff) * 2;
                ldsm4(ah[mt], uAh + off);
                ldsm4(al[mt], uAl + off);
            }
#pragma unroll
            for (int np = 0; np < 4; np++) {
                int mat = lane >> 3;
                int row = wn + np * 16 + ((mat >> 1) << 3) + (lane & 7);
                int koff = ks * 16 + ((mat & 1) << 3);
                uint32_t off = (uint32_t)(row * PITCH + koff) * 2;
                uint32_t bh[4], bl[4];
                ldsm4(bh, uBh + off);
                ldsm4(bl, uBl + off);
#pragma unroll
                for (int mt = 0; mt < 2; mt++) {
                    mma_bf16(acc[mt][np * 2],     ah[mt], &bh[0]);
                    mma_bf16(acc[mt][np * 2],     ah[mt], &bl[0]);
                    mma_bf16(acc[mt][np * 2],     al[mt], &bh[0]);
                    mma_bf16(acc[mt][np * 2 + 1], ah[mt], &bh[2]);
                    mma_bf16(acc[mt][np * 2 + 1], ah[mt], &bl[2]);
                    mma_bf16(acc[mt][np * 2 + 1], al[mt], &bh[2]);
                }
            }
        }
        __syncthreads();
    }

    // epilogue: P1 (fp16), P3 (fp32), rtb (fp16); all ld = 128
    const int tr = lane >> 2;
    const int tc = (lane & 3) * 2;
    const bool toP3 = (m0 && bn == 128);
    __half* Ch = m0 ? d_P1h : d_rtbh;
#pragma unroll
    for (int mt = 0; mt < 2; mt++) {
        int grow0 = bm + wm + mt * 16 + tr;
        int grow1 = grow0 + 8;
#pragma unroll
        for (int nt = 0; nt < 8; nt++) {
            int lcol = wn + nt * 8 + tc;
            if (toP3) {
                if (grow0 < M)
                    *reinterpret_cast<float2*>(&d_P3[(size_t)grow0 * DIM + lcol]) =
                        make_float2(acc[mt][nt][0], acc[mt][nt][1]);
                if (grow1 < M)
                    *reinterpret_cast<float2*>(&d_P3[(size_t)grow1 * DIM + lcol]) =
                        make_float2(acc[mt][nt][2], acc[mt][nt][3]);
            } else {
                if (grow0 < M)
                    *reinterpret_cast<__half2*>(&Ch[(size_t)grow0 * DIM + lcol]) =
                        __floats2half2_rn(acc[mt][nt][0], acc[mt][nt][1]);
                if (grow1 < M)
                    *reinterpret_cast<__half2*>(&Ch[(size_t)grow1 * DIM + lcol]) =
                        __floats2half2_rn(acc[mt][nt][2], acc[mt][nt][3]);
            }
        }
    }
}

// ---------------- counting sort by dst -----------------------------
__global__ void k_count(const int* __restrict__ edges) {
    int e = blockIdx.x * blockDim.x + threadIdx.x;
    if (e >= NEDGES) return;
    int4 ed = reinterpret_cast<const int4*>(edges)[e];
    atomicAdd(&d_counts[ed.y], 1);
}

// ---- two-level scan: block sums -> scan sums -> final offsets ----
__global__ __launch_bounds__(256) void k_bsum() {
    int i = blockIdx.x * 256 + threadIdx.x;
    int lane = threadIdx.x & 31, w = threadIdx.x >> 5;
    int v = (i < NNODES) ? d_counts[i] : 0;
#pragma unroll
    for (int o = 16; o > 0; o >>= 1) v += __shfl_down_sync(0xFFFFFFFFu, v, o);
    __shared__ int ws[8];
    if (lane == 0) ws[w] = v;
    __syncthreads();
    if (threadIdx.x == 0) {
        int s = 0;
#pragma unroll
        for (int j = 0; j < 8; j++) s += ws[j];
        d_bsums[blockIdx.x] = s;
    }
}

__global__ __launch_bounds__(256) void k_scanb() {
    int t = threadIdx.x;
    int lane = t & 31, w = t >> 5;
    int v = (t < NBLK) ? d_bsums[t] : 0;
    int inc = v;
#pragma unroll
    for (int o = 1; o < 32; o <<= 1) {
        int u = __shfl_up_sync(0xFFFFFFFFu, inc, o);
        if (lane >= o) inc += u;
    }
    __shared__ int ws[8];
    if (lane == 31) ws[w] = inc;
    __syncthreads();
    if (w == 0 && lane < 8) {
        int s = ws[lane];
#pragma unroll
        for (int o = 1; o < 8; o <<= 1) {
            int u = __shfl_up_sync(0xFFu, s, o);
            if (lane >= o) s += u;
        }
        ws[lane] = s;
    }
    __syncthreads();
    int excl = inc - v + (w > 0 ? ws[w - 1] : 0);
    if (t < NBLK) d_bsums[t] = excl;
}

__global__ __launch_bounds__(256) void k_scanfin() {
    int b = blockIdx.x;
    int i = b * 256 + threadIdx.x;
    int lane = threadIdx.x & 31, w = threadIdx.x >> 5;
    int v = (i < NNODES) ? d_counts[i] : 0;
    int inc = v;
#pragma unroll
    for (int o = 1; o < 32; o <<= 1) {
        int u = __shfl_up_sync(0xFFFFFFFFu, inc, o);
        if (lane >= o) inc += u;
    }
    __shared__ int ws[8];
    if (lane == 31) ws[w] = inc;
    __syncthreads();
    if (w == 0 && lane < 8) {
        int s = ws[lane];
#pragma unroll
        for (int o = 1; o < 8; o <<= 1) {
            int u = __shfl_up_sync(0xFFu, s, o);
            if (lane >= o) s += u;
        }
        ws[lane] = s;
    }
    __syncthreads();
    int excl = inc - v + (w > 0 ? ws[w - 1] : 0) + d_bsums[b];
    if (i < NNODES) {
        d_offsets[i] = excl;
        d_cursor[i] = excl;
        if (i == NNODES - 1) d_offsets[NNODES] = excl + v;
    }
}

__global__ void k_scatter(const int* __restrict__ edges) {
    int e = blockIdx.x * blockDim.x + threadIdx.x;
    if (e >= NEDGES) return;
    int4 ed = reinterpret_cast<const int4*>(edges)[e];
    int pos = atomicAdd(&d_cursor[ed.y], 1);
    d_ssrc[pos] = ed.x;
    d_spair[pos] = ed.z * NTS + ed.w;
}

// ---------------- aggregation: warp per node, fp16 gathers --------
__global__ __launch_bounds__(256) void k_agg(float* __restrict__ out,
                                             const float* __restrict__ b_fc) {
    int warp = (blockIdx.x * blockDim.x + threadIdx.x) >> 5;
    int lane = threadIdx.x & 31;
    if (warp >= NNODES) return;

    int s0 = d_offsets[warp];
    int s1 = d_offsets[warp + 1];

    const uint2* P1 = reinterpret_cast<const uint2*>(d_P1h);   // 32 uint2 / row
    const uint2* R  = reinterpret_cast<const uint2*>(d_rtbh);  // 32 uint2 / row
    const float4* P3 = reinterpret_cast<const float4*>(d_P3);  // 32 float4 / row

    float4 bias4 = reinterpret_cast<const float4*>(b_fc)[lane];
    float4 c3 = P3[warp * 32 + lane];
    c3.x += bias4.x; c3.y += bias4.y; c3.z += bias4.z; c3.w += bias4.w;

    float ax = 0.f, ay = 0.f, az = 0.f, aw = 0.f;
    int i = s0;
    for (; i + 2 <= s1; i += 2) {
        int sA = __ldg(&d_ssrc[i]);
        int sB = __ldg(&d_ssrc[i + 1]);
        int pA = __ldg(&d_spair[i]);
        int pB = __ldg(&d_spair[i + 1]);
        uint2 a0 = __ldg(&P1[sA * 32 + lane]);
        uint2 r0 = __ldg(&R[pA * 32 + lane]);
        uint2 a1 = __ldg(&P1[sB * 32 + lane]);
        uint2 r1 = __ldg(&R[pB * 32 + lane]);
        float2 a0lo = __half22float2(*reinterpret_cast<const __half2*>(&a0.x));
        float2 a0hi = __half22float2(*reinterpret_cast<const __half2*>(&a0.y));
        float2 r0lo = __half22float2(*reinterpret_cast<const __half2*>(&r0.x));
        float2 r0hi = __half22float2(*reinterpret_cast<const __half2*>(&r0.y));
        float2 a1lo = __half22float2(*reinterpret_cast<const __half2*>(&a1.x));
        float2 a1hi = __half22float2(*reinterpret_cast<const __half2*>(&a1.y));
        float2 r1lo = __half22float2(*reinterpret_cast<const __half2*>(&r1.x));
        float2 r1hi = __half22float2(*reinterpret_cast<const __half2*>(&r1.y));
        ax += lrelu(a0lo.x + r0lo.x + c3.x) + lrelu(a1lo.x + r1lo.x + c3.x);
        ay += lrelu(a0lo.y + r0lo.y + c3.y) + lrelu(a1lo.y + r1lo.y + c3.y);
        az += lrelu(a0hi.x + r0hi.x + c3.z) + lrelu(a1hi.x + r1hi.x + c3.z);
        aw += lrelu(a0hi.y + r0hi.y + c3.w) + lrelu(a1hi.y + r1hi.y + c3.w);
    }
    if (i < s1) {
        int s = __ldg(&d_ssrc[i]);
        int pr = __ldg(&d_spair[i]);
        uint2 a0 = __ldg(&P1[s * 32 + lane]);
        uint2 r0 = __ldg(&R[pr * 32 + lane]);
        float2 a0lo = __half22float2(*reinterpret_cast<const __half2*>(&a0.x));
        float2 a0hi = __half22float2(*reinterpret_cast<const __half2*>(&a0.y));
        float2 r0lo = __half22float2(*reinterpret_cast<const __half2*>(&r0.x));
        float2 r0hi = __half22float2(*reinterpret_cast<const __half2*>(&r0.y));
        ax += lrelu(a0lo.x + r0lo.x + c3.x);
        ay += lrelu(a0lo.y + r0lo.y + c3.y);
        az += lrelu(a0hi.x + r0hi.x + c3.z);
        aw += lrelu(a0hi.y + r0hi.y + c3.w);
    }
    int cnt = s1 - s0;
    float inv = 1.0f / (float)(cnt > 0 ? cnt : 1);
    float4 r;
    r.x = ax * inv; r.y = ay * inv; r.z = az * inv; r.w = aw * inv;
    reinterpret_cast<float4*>(out)[warp * 32 + lane] = r;
}

// ---------------- launcher ----------------------------------------
extern "C" void kernel_launch(void* const* d_in, const int* in_sizes, int n_in,
                              void* d_out, int out_size) {
    const float* x          = (const float*)d_in[0];
    const float* rel_table  = (const float*)d_in[1];
    const float* time_table = (const float*)d_in[2];
    const float* W_rt       = (const float*)d_in[3];
    const float* b_rt       = (const float*)d_in[4];
    const float* W_fc       = (const float*)d_in[5];
    const float* b_fc       = (const float*)d_in[6];
    const int*   edges      = (const int*)d_in[7];
    float* out = (float*)d_out;

    cudaFuncSetAttribute(hmma_all, cudaFuncAttributeMaxDynamicSharedMemorySize, SM_TOTAL);

    // side stream + fork/join events (created once, before first capture)
    static cudaStream_t s1 = nullptr;
    static cudaEvent_t evFork = nullptr, evJoin = nullptr;
    if (!s1) {
        cudaStreamCreateWithFlags(&s1, cudaStreamNonBlocking);
        cudaEventCreateWithFlags(&evFork, cudaEventDisableTiming);
        cudaEventCreateWithFlags(&evJoin, cudaEventDisableTiming);
    }

    void* pCounts;
    cudaGetSymbolAddress(&pCounts, d_counts);

    // ---- fork: sort chain on side stream, GEMM chain on main ----
    cudaEventRecord(evFork, 0);
    cudaStreamWaitEvent(s1, evFork, 0);

    cudaMemsetAsync(pCounts, 0, NNODES * sizeof(int), s1);
    k_count<<<(NEDGES + 255) / 256, 256, 0, s1>>>(edges);
    k_bsum<<<NBLK, 256, 0, s1>>>();
    k_scanb<<<1, 256, 0, s1>>>();
    k_scanfin<<<NBLK, 256, 0, s1>>>();
    k_scatter<<<(NEDGES + 255) / 256, 256, 0, s1>>>(edges);
    cudaEventRecord(evJoin, s1);

    // main stream: prep + both GEMMs
    k_prep<<<NREL + NTS + 192, 256>>>(rel_table, time_table, W_rt, W_fc);
    hmma_all<<<NB0 + NB1, 256, SM_TOTAL>>>(x, b_rt);

    // ---- join: aggregation needs both chains ----
    cudaStreamWaitEvent(0, evJoin, 0);
    k_agg<<<(NNODES * 32 + 255) / 256, 256>>>(out, b_fc);
}